// round 11
// baseline (speedup 1.0000x reference)
#include <cuda_runtime.h>
#include <cuda_fp16.h>
#include <math.h>
#include <stdint.h>

// Problem constants
#define BB    256
#define SS    128
#define IN_D  192
#define MLP_O 256
#define HH    1024
#define AA    64
#define K2    1280          // MLP_O + HH (o_prev folded away)
#define G4    4096
#define NCTA  128

// lstm smem geometry — W persistent + per-pair unit stages
#define W_HALFS  (20 * 64 * 64)        // 81920 halfs = 160 KB (20 K64-chunks)
#define USTG_B   1536                  // bytes per unit stage (32 rows x 48B, 32B data)
#define PAIR_B   (8 * USTG_B)          // 12288 B per pair (8 unit stages = 2 blocks)
#define SMEM_BYTES (W_HALFS * 2 + 4 * PAIR_B)   // 212992 B

// ---------------- device scratch ----------------
__device__ __align__(16) float g_WcT[IN_D * MLP_O];
__device__ float g_bc[MLP_O];
__device__ float g_bias0[G4];        // b_ih + b_hh             (t == 0)
__device__ float g_bias1[G4];        // + W_ihA @ bout          (t >= 1)
__device__ __align__(16) __half g_Wph[64 * W_HALFS];              // packed swizzled fp16 W
__device__ __align__(16) __half g_Ah[(size_t)(SS + 1) * BB * K2]; // [t][b][k] slabs fp16
__device__ unsigned g_step[NCTA];    // per-CTA monotonic step counter (single producer)
__device__ unsigned g_cnt = 0;
__device__ unsigned g_gen = 0;

__device__ __forceinline__ uint32_t smem_u32(const void* p)
{
    uint32_t a;
    asm("{ .reg .u64 t; cvta.to.shared.u64 t, %1; cvt.u32.u64 %0, t; }" : "=r"(a) : "l"(p));
    return a;
}

__device__ __forceinline__ void cpasync16(uint32_t dst, const void* src)
{
    asm volatile("cp.async.cg.shared.global [%0], [%1], 16;" :: "r"(dst), "l"(src));
}
#define CP_COMMIT() asm volatile("cp.async.commit_group;")
#define CP_WAIT(N)  asm volatile("cp.async.wait_group %0;" :: "n"(N))

__device__ __forceinline__ void ldsm4(uint32_t r[4], uint32_t addr)
{
    asm volatile("ldmatrix.sync.aligned.m8n8.x4.shared.b16 {%0,%1,%2,%3}, [%4];"
                 : "=r"(r[0]), "=r"(r[1]), "=r"(r[2]), "=r"(r[3]) : "r"(addr));
}

__device__ __forceinline__ void mma_f16(float c[4],
                                        uint32_t a0, uint32_t a1, uint32_t a2, uint32_t a3,
                                        uint32_t b0, uint32_t b1)
{
    asm("mma.sync.aligned.m16n8k16.row.col.f32.f16.f16.f32 "
        "{%0,%1,%2,%3}, {%4,%5,%6,%7}, {%8,%9}, {%0,%1,%2,%3};"
        : "+f"(c[0]), "+f"(c[1]), "+f"(c[2]), "+f"(c[3])
        : "r"(a0), "r"(a1), "r"(a2), "r"(a3), "r"(b0), "r"(b1));
}

__device__ __forceinline__ float fast_sig(float x)
{
    return 1.f / (1.f + __expf(-x));
}
__device__ __forceinline__ float fast_tanh(float x)
{
    x = fminf(fmaxf(x, -15.f), 15.f);
    float e = __expf(2.f * x);
    return (e - 1.f) / (e + 1.f);
}

// ---------------- full grid barrier (init only) ----------------
__device__ __forceinline__ void grid_barrier(unsigned &gen)
{
    __syncthreads();
    if (threadIdx.x == 0) {
        __threadfence();
        unsigned ticket = atomicAdd(&g_cnt, 1u);
        if (ticket == NCTA - 1u) {
            g_cnt = 0u;
            __threadfence();
            atomicAdd(&g_gen, 1u);
        } else {
            while (*((volatile unsigned *)&g_gen) == gen) { }
            __threadfence();
        }
    }
    gen += 1u;
    __syncthreads();
}

// ---------------- kernel 0: biases ----------------
__global__ void bias_kernel(const float* __restrict__ W2, const float* __restrict__ b1,
                            const float* __restrict__ b2, const float* __restrict__ bih,
                            const float* __restrict__ bhh, const float* __restrict__ Wih,
                            const float* __restrict__ bout)
{
    int n = blockIdx.x * 256 + threadIdx.x;
    float base = bih[n] + bhh[n];
    float fold = 0.f;
    const float* wa = Wih + n * 320 + 256;
    #pragma unroll
    for (int a = 0; a < 64; a++) fold = fmaf(wa[a], bout[a], fold);
    g_bias0[n] = base;
    g_bias1[n] = base + fold;

    if (blockIdx.x == 0) {
        int tid = threadIdx.x;
        const float* w2r = W2 + tid * 1024;
        float acc = b2[tid];
        #pragma unroll 4
        for (int h = 0; h < 1024; h += 4) {
            float4 w = *(const float4*)(w2r + h);
            acc = fmaf(w.x, b1[h], acc);
            acc = fmaf(w.y, b1[h+1], acc);
            acc = fmaf(w.z, b1[h+2], acc);
            acc = fmaf(w.w, b1[h+3], acc);
        }
        g_bc[tid] = acc;
    }
}

// ---------------- kernel 1: collapse W2@W1 -> WcT[k][o] ----------------
__global__ void collapse_kernel(const float* __restrict__ W1, const float* __restrict__ W2)
{
    __shared__ float w1k[1024];
    int k = blockIdx.x;
    for (int h = threadIdx.x; h < 1024; h += 256) w1k[h] = W1[h * IN_D + k];
    __syncthreads();
    int o = threadIdx.x;
    const float* w2r = W2 + o * 1024;
    float acc = 0.f;
    #pragma unroll 4
    for (int h = 0; h < 1024; h += 4) {
        float4 w = *(const float4*)(w2r + h);
        acc = fmaf(w.x, w1k[h],   acc);
        acc = fmaf(w.y, w1k[h+1], acc);
        acc = fmaf(w.z, w1k[h+2], acc);
        acc = fmaf(w.w, w1k[h+3], acc);
    }
    g_WcT[k * MLP_O + o] = acc;
}

// ---------------- kernel 2: pack fused+folded weights (fp16, swizzled smem image) ----------------
__global__ void wprep_kernel(const float* __restrict__ Wih, const float* __restrict__ Whh,
                             const float* __restrict__ Wout)
{
    __shared__ float As[64 * 68];
    __shared__ float Wc[64 * 68];
    const int jb  = blockIdx.x;
    const int tid = threadIdx.x;
    __half* wp = g_Wph + (size_t)jb * W_HALFS;

    #pragma unroll
    for (int q = 0; q < 16; q++) {
        int idx = q * 256 + tid;
        int col = idx >> 6, a = idx & 63;
        int row = (col >> 4) * 1024 + jb * 16 + (col & 15);
        As[col * 68 + a] = Wih[row * 320 + 256 + a];
    }
    // part 1: k < 256
    #pragma unroll 4
    for (int q = 0; q < 64; q++) {
        int idx = q * 256 + tid;
        int col = idx >> 8, k = idx & 255;
        int row = (col >> 4) * 1024 + jb * 16 + (col & 15);
        int sw  = ((k >> 3) & 7) ^ (col & 7);
        wp[(k >> 6) * 4096 + col * 64 + sw * 8 + (k & 7)] = __float2half(Wih[row * 320 + k]);
    }
    __syncthreads();

    const int col = tid & 63;
    const int hq  = tid >> 6;
    const int row = (col >> 4) * 1024 + jb * 16 + (col & 15);
    for (int hc = 0; hc < 16; hc++) {
        #pragma unroll 4
        for (int q = 0; q < 16; q++) {
            int idx = q * 256 + tid;
            int a = idx >> 6, h = idx & 63;
            Wc[a * 68 + h] = Wout[a * 1024 + hc * 64 + h];
        }
        __syncthreads();
        #pragma unroll 2
        for (int i = 0; i < 16; i++) {
            int h  = hq * 16 + i;
            int hh = hc * 64 + h;
            float fold = 0.f;
            #pragma unroll 8
            for (int a = 0; a < 64; a++)
                fold = fmaf(As[col * 68 + a], Wc[a * 68 + h], fold);
            float val = Whh[row * 1024 + hh] + fold;
            int k = 256 + hh;
            int sw = ((k >> 3) & 7) ^ (col & 7);
            wp[(k >> 6) * 4096 + col * 64 + sw * 8 + (k & 7)] = __float2half(val);
        }
        __syncthreads();
    }
}

// ---------------- kernel 3: mlp -> g_Ah[s][b][k] (fp16) ----------------
__global__ void mlp_kernel(const float* __restrict__ observe,
                           const float* __restrict__ obstacle,
                           const float* __restrict__ mask)
{
    __shared__ float xs[16 * IN_D];
    __shared__ __half hs[16 * 272];
    const int tid = threadIdx.x;
    const int s   = blockIdx.x >> 4;
    const int b0  = (blockIdx.x & 15) * 16;
    for (int idx = tid; idx < 16 * IN_D; idx += 256) {
        int i = idx / IN_D, k = idx - i * IN_D;
        int p = (b0 + i) * 128 + s;
        float v;
        if (k < 64) v = observe[p * 64 + k];
        else {
            int kk = k - 64;
            v = obstacle[p * 128 + kk] * mask[p * 8 + (kk >> 4)];
        }
        xs[i * IN_D + k] = v;
    }
    __syncthreads();

    float acc[16];
    #pragma unroll
    for (int i = 0; i < 16; i++) acc[i] = 0.f;
    #pragma unroll 4
    for (int k = 0; k < IN_D; k++) {
        float w = g_WcT[k * MLP_O + tid];
        #pragma unroll
        for (int i = 0; i < 16; i++)
            acc[i] = fmaf(xs[i * IN_D + k], w, acc[i]);
    }
    float bcv = g_bc[tid];
    #pragma unroll
    for (int i = 0; i < 16; i++)
        hs[i * 272 + tid] = __float2half(fmaxf(acc[i] + bcv, 0.f));
    __syncthreads();
    int i2 = tid >> 4, seg = tid & 15;
    uint4 v0 = *(uint4*)&hs[i2 * 272 + seg * 16];
    uint4 v1 = *(uint4*)&hs[i2 * 272 + seg * 16 + 8];
    __half* dst = g_Ah + (size_t)s * BB * K2 + (size_t)(b0 + i2) * K2 + seg * 16;
    *(uint4*)dst = v0;
    *(uint4*)(dst + 8) = v1;
}

// ---------------- kernel 4: persistent LSTM (ring dataflow, no per-step barrier) ----------------
__global__ void __launch_bounds__(256, 1)
lstm_kernel(int dummy)
{
    extern __shared__ __half smh[];
    float* sg = (float*)(smh + W_HALFS);     // epilogue alias of A stage region (49KB)
    __shared__ float sbias[2][64];

    const int tid  = threadIdx.x;
    const int cta  = blockIdx.x;
    const int mh   = cta & 1;                // batch half
    const int jb   = cta >> 1;               // j block (16 j's) == ring start
    const int j0   = jb * 16;
    const int lane = tid & 31;
    const int w    = tid >> 5;
    const int wm   = w & 3;                  // M quarter (32 rows) == pair id
    const int wn   = w >> 2;                 // N half (32 cols)
    unsigned gen = *((volatile unsigned*)&g_gen);

    const uint32_t sbase = smem_u32(smh);
    const uint32_t wbase = sbase;
    const uint32_t abase = sbase + W_HALFS * 2 + wm * PAIR_B;

    // ---- load persistent W (swizzled image, straight copy) ----
    {
        const __half* src = g_Wph + (size_t)jb * W_HALFS;
        for (int u = tid; u < W_HALFS / 8; u += 256)
            cpasync16(wbase + u * 16, src + (size_t)u * 8);
        CP_COMMIT();
    }

    // ---- init: slab0 h-part = 0, flags = 0, sbias; c in registers ----
    const int gt = cta * 256 + tid;
    for (int i = gt; i < (HH * BB) / 2; i += NCTA * 256) {
        int b = i >> 9, off = (i & 511) * 2;
        *(uint32_t*)&g_Ah[(size_t)b * K2 + 256 + off] = 0u;
    }
    if (gt < NCTA) g_step[gt] = 0u;
    if (tid < 64) {
        int gate = tid >> 4, jl = tid & 15;
        sbias[0][tid] = g_bias0[gate * 1024 + j0 + jl];
        sbias[1][tid] = g_bias1[gate * 1024 + j0 + jl];
    }
    float c_reg[8];
    #pragma unroll
    for (int q = 0; q < 8; q++) c_reg[q] = 0.f;
    CP_WAIT(0);
    grid_barrier(gen);     // init only; mainloop is pure dataflow

    // pair barrier: warps {wm, wm+4}, 64 threads, named barrier wm+1
    #define BAR_PAIR() asm volatile("bar.sync %0, %1;" :: "r"(wm + 1), "r"(64) : "memory")

    // unit id: d<4 -> mlp units (k<256); d>=4 -> h units in ring order from jb
    auto unit_of = [&](int d, int i) -> int {
        return (d < 4) ? (d * 4 + i) : (16 + ((jb + (d - 4) * 4 + i) & 63));
    };

    // prefetch one block (4 units) of step t into parity (d&1) stages
    auto prefBlock = [&](const __half* Asl, int tneed, int d) {
        if (d >= 4) {
            if (lane < 4) {
                int g = (jb + (d - 4) * 4 + lane) & 63;
                const volatile unsigned* f = &g_step[g * 2 + mh];
                while (*f < (unsigned)tneed) { }
            }
            __syncwarp();
            __threadfence();
        }
        const int pl = wn * 32 + lane;       // 0..63 within pair
        const int hh2 = pl >> 5, rr = pl & 31;
        uint32_t sd0 = abase + (d & 1) * (4 * USTG_B) + 48 * rr + 16 * hh2;
        const __half* srcB = Asl + (size_t)(wm * 32 + rr) * K2 + hh2 * 8;
        #pragma unroll
        for (int i = 0; i < 4; i++) {
            int u = unit_of(d, i);
            cpasync16(sd0 + i * USTG_B, srcB + u * 16);
        }
        CP_COMMIT();
    };

    // compute one block (4 K=16 units)
    auto doBlock = [&](int d, float (&acc)[2][4][4]) {
        #pragma unroll
        for (int i = 0; i < 4; i++) {
            int u = unit_of(d, i);
            int cc = u >> 2, ks = u & 3;
            uint32_t sA = abase + ((d & 1) * 4 + i) * USTG_B;
            uint32_t sB = wbase + cc * 8192;
            int ku0 = ks * 2;
            uint32_t af[2][4], bf[2][4];
            #pragma unroll
            for (int mt = 0; mt < 2; mt++)
                ldsm4(af[mt], sA + 48 * (mt * 16 + (lane & 15)) + 16 * (lane >> 4));
            #pragma unroll
            for (int nh = 0; nh < 2; nh++) {
                int n  = wn * 32 + nh * 16 + (lane & 7) + ((lane >> 4) << 3);
                int ku = ((lane & 8) >> 3) + ku0;
                ldsm4(bf[nh], sB + n * 128 + ((ku ^ (n & 7)) << 4));
            }
            #pragma unroll
            for (int mt = 0; mt < 2; mt++)
                #pragma unroll
                for (int nt = 0; nt < 4; nt++)
                    mma_f16(acc[mt][nt],
                            af[mt][0], af[mt][1], af[mt][2], af[mt][3],
                            bf[nt >> 1][(nt & 1) * 2], bf[nt >> 1][(nt & 1) * 2 + 1]);
        }
    };

    // prime: step 0 block 0 (mlp, no deps)
    prefBlock(g_Ah + (size_t)mh * 128 * K2, 0, 0);

    for (int t = 0; t < SS; ++t) {
        const __half* Asl = g_Ah + (size_t)t * BB * K2 + (size_t)mh * 128 * K2;

        float acc[2][4][4];
        #pragma unroll
        for (int mt = 0; mt < 2; mt++)
            #pragma unroll
            for (int nt = 0; nt < 4; nt++)
                #pragma unroll
                for (int r = 0; r < 4; r++) acc[mt][nt][r] = 0.f;

        // ---- 20 blocks, ring-ordered h units, distance-1 pipeline ----
        for (int d = 0; d < 20; d++) {
            CP_WAIT(0);        // block d landed
            BAR_PAIR();        // partner done with block d-1's stages + sees block d
            if (d < 19) prefBlock(Asl, t, d + 1);
            doBlock(d, acc);
        }
        __syncthreads();   // all pairs done -> stage region reusable as sg

        // ---- epilogue: acc -> sg[col][m] (fp32) ----
        #pragma unroll
        for (int mt = 0; mt < 2; mt++) {
            int m0 = wm * 32 + mt * 16 + (lane >> 2);
            #pragma unroll
            for (int nt = 0; nt < 4; nt++) {
                int c0 = wn * 32 + nt * 8 + 2 * (lane & 3);
                sg[c0 * 132 + m0]           = acc[mt][nt][0];
                sg[(c0 + 1) * 132 + m0]     = acc[mt][nt][1];
                sg[c0 * 132 + m0 + 8]       = acc[mt][nt][2];
                sg[(c0 + 1) * 132 + m0 + 8] = acc[mt][nt][3];
            }
        }
        __syncthreads();

        // ---- cell update (c in registers) ----
        {
            const int b  = tid & 127;
            const int js = (tid >> 7) * 8;
            const float* bs = sbias[t > 0 ? 1 : 0];
            __align__(16) __half hbuf[8];
            #pragma unroll
            for (int q = 0; q < 8; q++) {
                int jl = js + q;
                float iv = fast_sig (sg[jl * 132 + b]        + bs[jl]);
                float fv = fast_sig (sg[(16 + jl) * 132 + b] + bs[16 + jl]);
                float gv = fast_tanh(sg[(32 + jl) * 132 + b] + bs[32 + jl]);
                float ov = fast_sig (sg[(48 + jl) * 132 + b] + bs[48 + jl]);
                float cnew = fmaf(fv, c_reg[q], iv * gv);
                c_reg[q] = cnew;
                hbuf[q] = __float2half(ov * fast_tanh(cnew));
            }
            __half* hd = g_Ah + (size_t)(t + 1) * BB * K2
                       + (size_t)(mh * 128 + b) * K2 + 256 + j0 + js;
            *(uint4*)hd = *(uint4*)hbuf;
        }
        __syncthreads();   // all h stores + sg reads complete

        // ---- release flag + prime next step's mlp block 0 ----
        if (t + 1 < SS) {
            if (tid == 0) {
                __threadfence();
                *((volatile unsigned*)&g_step[cta]) = (unsigned)(t + 1);
            }
            prefBlock(Asl + (size_t)BB * K2, t + 1, 0);
        }
    }
    #undef BAR_PAIR
}

// ---------------- kernel 5: out[b][t][a] = h_t @ Wout^T + bout ----------------
__global__ void finalout_kernel(const float* __restrict__ Wout,
                                const float* __restrict__ bout,
                                float* __restrict__ dout)
{
    __shared__ float sH[128 * 33];
    __shared__ float sWT[32 * 68];
    const int tid = threadIdx.x;
    const int tt  = blockIdx.x >> 1;
    const int b0  = (blockIdx.x & 1) * 128;
    const int b   = tid & 127;
    const int ab  = (tid >> 7) * 32;

    const __half* hsl = g_Ah + (size_t)(tt + 1) * BB * K2;

    float acc[32];
    #pragma unroll
    for (int r = 0; r < 32; r++) acc[r] = 0.f;

    for (int jc = 0; jc < 32; jc++) {
        #pragma unroll
        for (int q = 0; q < 16; q++) {
            int idx = q * 256 + tid;
            int row = idx >> 5, j = idx & 31;
            sH[row * 33 + j] = __half2float(hsl[(size_t)(b0 + row) * K2 + 256 + jc * 32 + j]);
        }
        #pragma unroll
        for (int q = 0; q < 8; q++) {
            int idx = q * 256 + tid;
            int a = idx >> 5, j = idx & 31;
            sWT[j * 68 + a] = Wout[a * 1024 + jc * 32 + j];
        }
        __syncthreads();
        #pragma unroll 4
        for (int k = 0; k < 32; k++) {
            float av = sH[b * 33 + k];
            const float4* wp = (const float4*)(sWT + k * 68 + ab);
            #pragma unroll
            for (int r = 0; r < 8; r++) {
                float4 wv = wp[r];
                acc[r*4+0] = fmaf(av, wv.x, acc[r*4+0]);
                acc[r*4+1] = fmaf(av, wv.y, acc[r*4+1]);
                acc[r*4+2] = fmaf(av, wv.z, acc[r*4+2]);
                acc[r*4+3] = fmaf(av, wv.w, acc[r*4+3]);
            }
        }
        __syncthreads();
    }
    float* dp = dout + (size_t)(b0 + b) * SS * AA + tt * AA + ab;
    #pragma unroll
    for (int r = 0; r < 32; r++) dp[r] = acc[r] + bout[ab + r];
}

// ---------------- launch ----------------
extern "C" void kernel_launch(void* const* d_in, const int* in_sizes, int n_in,
                              void* d_out, int out_size)
{
    const float* observe  = (const float*)d_in[0];
    const float* obstacle = (const float*)d_in[1];
    const float* mask     = (const float*)d_in[2];
    const float* W1       = (const float*)d_in[3];
    const float* b1       = (const float*)d_in[4];
    const float* W2       = (const float*)d_in[5];
    const float* b2       = (const float*)d_in[6];
    const float* W_ih     = (const float*)d_in[7];
    const float* b_ih     = (const float*)d_in[8];
    const float* W_hh     = (const float*)d_in[9];
    const float* b_hh     = (const float*)d_in[10];
    const float* W_out    = (const float*)d_in[11];
    const float* b_out    = (const float*)d_in[12];
    float* out = (float*)d_out;

    cudaFuncSetAttribute(lstm_kernel, cudaFuncAttributeMaxDynamicSharedMemorySize, SMEM_BYTES);

    bias_kernel<<<16, 256>>>(W2, b1, b2, b_ih, b_hh, W_ih, b_out);
    collapse_kernel<<<IN_D, 256>>>(W1, W2);
    wprep_kernel<<<64, 256>>>(W_ih, W_hh, W_out);
    mlp_kernel<<<SS * 16, 256>>>(observe, obstacle, mask);
    lstm_kernel<<<NCTA, 256, SMEM_BYTES>>>(0);
    finalout_kernel<<<SS * 2, 256>>>(W_out, b_out, out);
}

// round 12
// speedup vs baseline: 1.9588x; 1.9588x over previous
#include <cuda_runtime.h>
#include <cuda_fp16.h>
#include <math.h>
#include <stdint.h>

// Problem constants
#define BB    256
#define SS    128
#define IN_D  192
#define MLP_O 256
#define HH    1024
#define AA    64
#define K2    1280          // MLP_O + HH (o_prev folded away)
#define CK    64            // K per chunk
#define NCH   20            // K2/CK  (chunks 0..3 = mlp part, 4..19 = h part)
#define G4    4096
#define NCTA  128

// lstm smem geometry (halfs) — W persistent + per-pair swizzled A stages
#define W_HALFS  (NCH * 64 * CK)       // 81920 halfs = 160 KB
#define ASTG2_B  4096                  // bytes per pair stage (32 rows x 64 halfs)
#define NSTG     4
#define A_HALFS  (4 * NSTG * (ASTG2_B / 2))              // 32768 halfs = 64 KB
#define SMEM_BYTES ((W_HALFS + A_HALFS) * 2)             // 229376 B

// finalout smem: Wout image (16 chunks x 4096 halfs = 128 KB) + 2 H stages (16 KB each)
#define FW_HALFS  (16 * 64 * 64)                          // 65536 halfs = 128 KB
#define FSTG_B    16384                                   // 128 rows x 128 B
#define FOUT_SMEM (FW_HALFS * 2 + 2 * FSTG_B)             // 163840 B

// ---------------- device scratch ----------------
__device__ __align__(16) float g_WcT[IN_D * MLP_O];
__device__ float g_bc[MLP_O];
__device__ float g_bias0[G4];        // b_ih + b_hh             (t == 0)
__device__ float g_bias1[G4];        // + W_ihA @ bout          (t >= 1)
__device__ __align__(16) __half g_Wph[64 * W_HALFS];              // packed swizzled fp16 W
__device__ __align__(16) __half g_Wfin[FW_HALFS];                 // packed swizzled fp16 Wout
__device__ __align__(16) __half g_Ah[(size_t)(SS + 1) * BB * K2]; // [t][b][k] slabs fp16
__device__ unsigned g_cnt = 0;
__device__ unsigned g_gen = 0;

__device__ __forceinline__ uint32_t smem_u32(const void* p)
{
    uint32_t a;
    asm("{ .reg .u64 t; cvta.to.shared.u64 t, %1; cvt.u32.u64 %0, t; }" : "=r"(a) : "l"(p));
    return a;
}

__device__ __forceinline__ void cpasync16(uint32_t dst, const void* src)
{
    asm volatile("cp.async.cg.shared.global [%0], [%1], 16;" :: "r"(dst), "l"(src));
}
#define CP_COMMIT() asm volatile("cp.async.commit_group;")
#define CP_WAIT(N)  asm volatile("cp.async.wait_group %0;" :: "n"(N))

__device__ __forceinline__ void ldsm4(uint32_t r[4], uint32_t addr)
{
    asm volatile("ldmatrix.sync.aligned.m8n8.x4.shared.b16 {%0,%1,%2,%3}, [%4];"
                 : "=r"(r[0]), "=r"(r[1]), "=r"(r[2]), "=r"(r[3]) : "r"(addr));
}

__device__ __forceinline__ void mma_f16(float c[4],
                                        uint32_t a0, uint32_t a1, uint32_t a2, uint32_t a3,
                                        uint32_t b0, uint32_t b1)
{
    asm("mma.sync.aligned.m16n8k16.row.col.f32.f16.f16.f32 "
        "{%0,%1,%2,%3}, {%4,%5,%6,%7}, {%8,%9}, {%0,%1,%2,%3};"
        : "+f"(c[0]), "+f"(c[1]), "+f"(c[2]), "+f"(c[3])
        : "r"(a0), "r"(a1), "r"(a2), "r"(a3), "r"(b0), "r"(b1));
}

__device__ __forceinline__ float fast_sig(float x)
{
    return 1.f / (1.f + __expf(-x));
}
__device__ __forceinline__ float fast_tanh(float x)
{
    x = fminf(fmaxf(x, -15.f), 15.f);
    float e = __expf(2.f * x);
    return (e - 1.f) / (e + 1.f);
}

// ---------------- full grid barrier (init only) ----------------
__device__ __forceinline__ void grid_barrier(unsigned &gen)
{
    __syncthreads();
    if (threadIdx.x == 0) {
        __threadfence();
        unsigned ticket = atomicAdd(&g_cnt, 1u);
        if (ticket == NCTA - 1u) {
            g_cnt = 0u;
            __threadfence();
            atomicAdd(&g_gen, 1u);
        } else {
            while (*((volatile unsigned *)&g_gen) == gen) { }
            __threadfence();
        }
    }
    gen += 1u;
    __syncthreads();
}

// ---------------- kernel 0: biases ----------------
__global__ void bias_kernel(const float* __restrict__ W2, const float* __restrict__ b1,
                            const float* __restrict__ b2, const float* __restrict__ bih,
                            const float* __restrict__ bhh, const float* __restrict__ Wih,
                            const float* __restrict__ bout)
{
    int n = blockIdx.x * 256 + threadIdx.x;
    float base = bih[n] + bhh[n];
    float fold = 0.f;
    const float* wa = Wih + n * 320 + 256;
    #pragma unroll
    for (int a = 0; a < 64; a++) fold = fmaf(wa[a], bout[a], fold);
    g_bias0[n] = base;
    g_bias1[n] = base + fold;

    if (blockIdx.x == 0) {
        int tid = threadIdx.x;
        const float* w2r = W2 + tid * 1024;
        float acc = b2[tid];
        #pragma unroll 4
        for (int h = 0; h < 1024; h += 4) {
            float4 w = *(const float4*)(w2r + h);
            acc = fmaf(w.x, b1[h], acc);
            acc = fmaf(w.y, b1[h+1], acc);
            acc = fmaf(w.z, b1[h+2], acc);
            acc = fmaf(w.w, b1[h+3], acc);
        }
        g_bc[tid] = acc;
    }
}

// ---------------- kernel 1: collapse W2@W1 -> WcT[k][o] ----------------
__global__ void collapse_kernel(const float* __restrict__ W1, const float* __restrict__ W2)
{
    __shared__ float w1k[1024];
    int k = blockIdx.x;
    for (int h = threadIdx.x; h < 1024; h += 256) w1k[h] = W1[h * IN_D + k];
    __syncthreads();
    int o = threadIdx.x;
    const float* w2r = W2 + o * 1024;
    float acc = 0.f;
    #pragma unroll 4
    for (int h = 0; h < 1024; h += 4) {
        float4 w = *(const float4*)(w2r + h);
        acc = fmaf(w.x, w1k[h],   acc);
        acc = fmaf(w.y, w1k[h+1], acc);
        acc = fmaf(w.z, w1k[h+2], acc);
        acc = fmaf(w.w, w1k[h+3], acc);
    }
    g_WcT[k * MLP_O + o] = acc;
}

// ---------------- kernel 2: pack fused+folded weights (fp16, swizzled smem image) ----------------
__global__ void wprep_kernel(const float* __restrict__ Wih, const float* __restrict__ Whh,
                             const float* __restrict__ Wout)
{
    __shared__ float As[64 * 68];
    __shared__ float Wc[64 * 68];
    const int jb  = blockIdx.x;
    const int tid = threadIdx.x;
    __half* wp = g_Wph + (size_t)jb * W_HALFS;

    #pragma unroll
    for (int q = 0; q < 16; q++) {
        int idx = q * 256 + tid;
        int col = idx >> 6, a = idx & 63;
        int row = (col >> 4) * 1024 + jb * 16 + (col & 15);
        As[col * 68 + a] = Wih[row * 320 + 256 + a];
    }
    // part 1: k < 256
    #pragma unroll 4
    for (int q = 0; q < 64; q++) {
        int idx = q * 256 + tid;
        int col = idx >> 8, k = idx & 255;
        int row = (col >> 4) * 1024 + jb * 16 + (col & 15);
        int sw  = ((k >> 3) & 7) ^ (col & 7);
        wp[(k >> 6) * 4096 + col * 64 + sw * 8 + (k & 7)] = __float2half(Wih[row * 320 + k]);
    }
    __syncthreads();

    const int col = tid & 63;
    const int hq  = tid >> 6;
    const int row = (col >> 4) * 1024 + jb * 16 + (col & 15);
    for (int hc = 0; hc < 16; hc++) {
        #pragma unroll 4
        for (int q = 0; q < 16; q++) {
            int idx = q * 256 + tid;
            int a = idx >> 6, h = idx & 63;
            Wc[a * 68 + h] = Wout[a * 1024 + hc * 64 + h];
        }
        __syncthreads();
        #pragma unroll 2
        for (int i = 0; i < 16; i++) {
            int h  = hq * 16 + i;
            int hh = hc * 64 + h;
            float fold = 0.f;
            #pragma unroll 8
            for (int a = 0; a < 64; a++)
                fold = fmaf(As[col * 68 + a], Wc[a * 68 + h], fold);
            float val = Whh[row * 1024 + hh] + fold;
            int k = 256 + hh;
            int sw = ((k >> 3) & 7) ^ (col & 7);
            wp[(k >> 6) * 4096 + col * 64 + sw * 8 + (k & 7)] = __float2half(val);
        }
        __syncthreads();
    }
}

// ---------------- kernel 2b: pack Wout fp16 swizzled image for finalout ----------------
__global__ void wfin_kernel(const float* __restrict__ Wout)
{
    const int cc  = blockIdx.x;          // 0..15 (K chunk)
    const int tid = threadIdx.x;
    __half* wp = g_Wfin + cc * 4096;
    #pragma unroll
    for (int q = 0; q < 16; q++) {
        int idx = q * 256 + tid;         // 0..4095
        int n = idx >> 6, kk = idx & 63;
        int sw = ((kk >> 3) & 7) ^ (n & 7);
        wp[n * 64 + sw * 8 + (kk & 7)] = __float2half(Wout[n * 1024 + cc * 64 + kk]);
    }
}

// ---------------- kernel 3: mlp -> g_Ah[s][b][k] (fp16) ----------------
__global__ void mlp_kernel(const float* __restrict__ observe,
                           const float* __restrict__ obstacle,
                           const float* __restrict__ mask)
{
    __shared__ float xs[16 * IN_D];
    __shared__ __half hs[16 * 272];
    const int tid = threadIdx.x;
    const int s   = blockIdx.x >> 4;
    const int b0  = (blockIdx.x & 15) * 16;
    for (int idx = tid; idx < 16 * IN_D; idx += 256) {
        int i = idx / IN_D, k = idx - i * IN_D;
        int p = (b0 + i) * 128 + s;
        float v;
        if (k < 64) v = observe[p * 64 + k];
        else {
            int kk = k - 64;
            v = obstacle[p * 128 + kk] * mask[p * 8 + (kk >> 4)];
        }
        xs[i * IN_D + k] = v;
    }
    __syncthreads();

    float acc[16];
    #pragma unroll
    for (int i = 0; i < 16; i++) acc[i] = 0.f;
    #pragma unroll 4
    for (int k = 0; k < IN_D; k++) {
        float w = g_WcT[k * MLP_O + tid];
        #pragma unroll
        for (int i = 0; i < 16; i++)
            acc[i] = fmaf(xs[i * IN_D + k], w, acc[i]);
    }
    float bcv = g_bc[tid];
    #pragma unroll
    for (int i = 0; i < 16; i++)
        hs[i * 272 + tid] = __float2half(fmaxf(acc[i] + bcv, 0.f));
    __syncthreads();
    int i2 = tid >> 4, seg = tid & 15;
    uint4 v0 = *(uint4*)&hs[i2 * 272 + seg * 16];
    uint4 v1 = *(uint4*)&hs[i2 * 272 + seg * 16 + 8];
    __half* dst = g_Ah + (size_t)s * BB * K2 + (size_t)(b0 + i2) * K2 + seg * 16;
    *(uint4*)dst = v0;
    *(uint4*)(dst + 8) = v1;
}

// ---------------- kernel 4: persistent LSTM (R10: warp-pair pipelines, reg-resident c) ----------------
__global__ void __launch_bounds__(256, 1)
lstm_kernel(int dummy)
{
    extern __shared__ __half smh[];
    float* sg = (float*)(smh + W_HALFS);     // epilogue alias of A stage region
    __shared__ float sbias[2][64];

    const int tid  = threadIdx.x;
    const int cta  = blockIdx.x;
    const int mh   = cta & 1;                // batch half
    const int jb   = cta >> 1;               // j block (16 j's)
    const int j0   = jb * 16;
    const int lane = tid & 31;
    const int w    = tid >> 5;
    const int wm   = w & 3;                  // M quarter (32 rows) == pair id
    const int wn   = w >> 2;                 // N half (32 cols)
    unsigned gen = *((volatile unsigned*)&g_gen);

    const uint32_t sbase = smem_u32(smh);
    const uint32_t wbase = sbase;
    const uint32_t abase = sbase + W_HALFS * 2;

    // ---- load persistent W (swizzled image, straight copy) ----
    {
        const __half* src = g_Wph + (size_t)jb * W_HALFS;
        for (int u = tid; u < W_HALFS / 8; u += 256)
            cpasync16(wbase + u * 16, src + (size_t)u * 8);
        CP_COMMIT();
    }

    // ---- init: slab0 h-part = 0, sbias; c lives in registers ----
    const int gt = cta * 256 + tid;
    for (int i = gt; i < (HH * BB) / 2; i += NCTA * 256) {
        int b = i >> 9, off = (i & 511) * 2;
        *(uint32_t*)&g_Ah[(size_t)b * K2 + 256 + off] = 0u;
    }
    if (tid < 64) {
        int gate = tid >> 4, jl = tid & 15;
        sbias[0][tid] = g_bias0[gate * 1024 + j0 + jl];
        sbias[1][tid] = g_bias1[gate * 1024 + j0 + jl];
    }
    float c_reg[8];
    #pragma unroll
    for (int q = 0; q < 8; q++) c_reg[q] = 0.f;
    CP_WAIT(0);
    grid_barrier(gen);

    // pair barrier: warps {wm, wm+4}, 64 threads, named barrier wm+1
    #define BAR_PAIR() asm volatile("bar.sync %0, %1;" :: "r"(wm + 1), "r"(64) : "memory")

    // pair A prefetch: both warps of the pair load half the 4KB sub-tile
    auto prefA = [&](const __half* Asl, int cc) {
        uint32_t sd = abase + (wm * NSTG + (cc & 3)) * ASTG2_B;
        const __half* src = Asl + (size_t)(wm * 32) * K2 + cc * CK;
        #pragma unroll
        for (int i = 0; i < 4; i++) {
            int idx = i * 64 + wn * 32 + lane;      // 0..255 unit id
            int r = idx >> 3, u = idx & 7;
            cpasync16(sd + r * 128 + ((u ^ (r & 7)) << 4), src + (size_t)r * K2 + u * 8);
        }
        CP_COMMIT();
    };

    // one K=64 chunk: pair stage (cc&3) + persistent W chunk cc
    auto do_chunk = [&](int cc, float (&acc)[2][4][4]) {
        uint32_t sA = abase + (wm * NSTG + (cc & 3)) * ASTG2_B;
        uint32_t sB = wbase + cc * 8192;
        #pragma unroll
        for (int ks = 0; ks < 4; ks++) {
            const int ku0 = ks * 2;
            uint32_t af[2][4], bf[2][4];
            #pragma unroll
            for (int mt = 0; mt < 2; mt++) {
                int lr = mt * 16 + (lane & 15);     // local row in pair tile
                int ku = (lane >> 4) + ku0;
                ldsm4(af[mt], sA + lr * 128 + ((ku ^ (lr & 7)) << 4));
            }
            #pragma unroll
            for (int nh = 0; nh < 2; nh++) {
                int n  = wn * 32 + nh * 16 + (lane & 7) + ((lane >> 4) << 3);
                int ku = ((lane & 8) >> 3) + ku0;
                ldsm4(bf[nh], sB + n * 128 + ((ku ^ (n & 7)) << 4));
            }
            #pragma unroll
            for (int mt = 0; mt < 2; mt++)
                #pragma unroll
                for (int nt = 0; nt < 4; nt++)
                    mma_f16(acc[mt][nt],
                            af[mt][0], af[mt][1], af[mt][2], af[mt][3],
                            bf[nt >> 1][(nt & 1) * 2], bf[nt >> 1][(nt & 1) * 2 + 1]);
        }
    };

    // prime: slab0 chunks 0,1,2 (mlp part, no cross-CTA dependency)
    prefA(g_Ah + (size_t)mh * 128 * K2, 0);
    prefA(g_Ah + (size_t)mh * 128 * K2, 1);
    prefA(g_Ah + (size_t)mh * 128 * K2, 2);

    for (int t = 0; t < SS; ++t) {
        const __half* Asl = g_Ah + (size_t)t * BB * K2 + (size_t)mh * 128 * K2;

        float acc[2][4][4];
        #pragma unroll
        for (int mt = 0; mt < 2; mt++)
            #pragma unroll
            for (int nt = 0; nt < 4; nt++)
                #pragma unroll
                for (int r = 0; r < 4; r++) acc[mt][nt][r] = 0.f;

        // ---- pre-wait region: mlp chunks 0..3 (pair-local pipeline) ----
        for (int cc = 0; cc < 4; cc++) {
            if (cc == 0) prefA(Asl, 3);          // last mlp chunk
            if      (cc == 0) CP_WAIT(3);
            else if (cc == 1) CP_WAIT(2);
            else if (cc == 2) CP_WAIT(1);
            else              CP_WAIT(0);
            BAR_PAIR();
            do_chunk(cc, acc);
        }

        // ---- global barrier wait (arrive happened at end of previous step) ----
        if (t > 0) {
            if (tid == 0) {
                while (*((volatile unsigned*)&g_gen) == gen) { }
                __threadfence();
            }
            gen += 1u;
        }
        __syncthreads();

        // ---- h chunks 4..19 (pair-local pipeline, distance-3 prefetch) ----
        prefA(Asl, 4);
        prefA(Asl, 5);
        prefA(Asl, 6);
        for (int cc = 4; cc < NCH; cc++) {
            if (cc + 3 < NCH) prefA(Asl, cc + 3);
            if      (cc <  NCH - 3) CP_WAIT(3);
            else if (cc == NCH - 3) CP_WAIT(2);
            else if (cc == NCH - 2) CP_WAIT(1);
            else                    CP_WAIT(0);
            BAR_PAIR();
            do_chunk(cc, acc);
        }
        __syncthreads();   // all pairs done -> stage region reusable as sg

        // ---- epilogue: acc -> sg[col][m] ----
        #pragma unroll
        for (int mt = 0; mt < 2; mt++) {
            int m0 = wm * 32 + mt * 16 + (lane >> 2);
            #pragma unroll
            for (int nt = 0; nt < 4; nt++) {
                int c0 = wn * 32 + nt * 8 + 2 * (lane & 3);
                sg[c0 * 132 + m0]           = acc[mt][nt][0];
                sg[(c0 + 1) * 132 + m0]     = acc[mt][nt][1];
                sg[c0 * 132 + m0 + 8]       = acc[mt][nt][2];
                sg[(c0 + 1) * 132 + m0 + 8] = acc[mt][nt][3];
            }
        }
        __syncthreads();

        // ---- cell update (c in registers) ----
        {
            const int b  = tid & 127;
            const int js = (tid >> 7) * 8;
            const float* bs = sbias[t > 0 ? 1 : 0];
            __align__(16) __half hbuf[8];
            #pragma unroll
            for (int q = 0; q < 8; q++) {
                int jl = js + q;
                float iv = fast_sig (sg[jl * 132 + b]        + bs[jl]);
                float fv = fast_sig (sg[(16 + jl) * 132 + b] + bs[16 + jl]);
                float gv = fast_tanh(sg[(32 + jl) * 132 + b] + bs[32 + jl]);
                float ov = fast_sig (sg[(48 + jl) * 132 + b] + bs[48 + jl]);
                float cnew = fmaf(fv, c_reg[q], iv * gv);
                c_reg[q] = cnew;
                hbuf[q] = __float2half(ov * fast_tanh(cnew));
            }
            __half* hd = g_Ah + (size_t)(t + 1) * BB * K2
                       + (size_t)(mh * 128 + b) * K2 + 256 + j0 + js;
            *(uint4*)hd = *(uint4*)hbuf;
        }
        __syncthreads();   // sg reads done before stages reused

        // ---- split-barrier arrive + prime next-step mlp chunks ----
        if (t + 1 < SS) {
            if (tid == 0) {
                __threadfence();
                unsigned ticket = atomicAdd(&g_cnt, 1u);
                if (ticket == NCTA - 1u) {
                    g_cnt = 0u;
                    __threadfence();
                    atomicAdd(&g_gen, 1u);
                }
            }
            const __half* AslN = Asl + (size_t)BB * K2;
            prefA(AslN, 0);
            prefA(AslN, 1);
            prefA(AslN, 2);
        }
    }
    #undef BAR_PAIR
}

// ---------------- kernel 5: out[b][t][a] = h_t @ Wout^T + bout (fp16 mma) ----------------
__global__ void __launch_bounds__(256, 1)
finalout_kernel(const float* __restrict__ bout, float* __restrict__ dout)
{
    extern __shared__ __half fsm[];
    const int tid  = threadIdx.x;
    const int lane = tid & 31;
    const int w    = tid >> 5;               // warp -> rows [w*16, w*16+16)
    const int tt   = blockIdx.x >> 1;
    const int b0   = (blockIdx.x & 1) * 128;

    const uint32_t sbase = smem_u32(fsm);
    const uint32_t wbase = sbase;                       // Wout image: 16 chunks x 8192 B
    const uint32_t hbase = sbase + FW_HALFS * 2;        // 2 H stages x 16384 B

    const __half* hsl = g_Ah + (size_t)(tt + 1) * BB * K2 + (size_t)b0 * K2 + 256;

    // load Wout image (128 KB)
    for (int u = tid; u < FW_HALFS / 8; u += 256)
        cpasync16(wbase + u * 16, g_Wfin + (size_t)u * 8);

    // prefetch H chunk 0
    auto prefH = [&](int cc) {
        uint32_t sd = hbase + (cc & 1) * FSTG_B;
        #pragma unroll
        for (int i = 0; i < 4; i++) {
            int idx = i * 256 + tid;         // 0..1023 units (128 rows x 8)
            int r = idx >> 3, u = idx & 7;
            cpasync16(sd + r * 128 + ((u ^ (r & 7)) << 4),
                      hsl + (size_t)r * K2 + cc * 64 + u * 8);
        }
        CP_COMMIT();
    };
    prefH(0);

    float acc[8][4];
    #pragma unroll
    for (int nt = 0; nt < 8; nt++)
        #pragma unroll
        for (int r = 0; r < 4; r++) acc[nt][r] = 0.f;

    for (int cc = 0; cc < 16; cc++) {
        if (cc + 1 < 16) { prefH(cc + 1); CP_WAIT(1); }
        else             { CP_WAIT(0); }
        __syncthreads();
        uint32_t sA = hbase + (cc & 1) * FSTG_B;
        uint32_t sB = wbase + cc * 8192;
        #pragma unroll
        for (int ks = 0; ks < 4; ks++) {
            const int ku0 = ks * 2;
            uint32_t af[4], bf[4][4];
            {
                int lr = w * 16 + (lane & 15);
                int ku = (lane >> 4) + ku0;
                ldsm4(af, sA + lr * 128 + ((ku ^ (lr & 7)) << 4));
            }
            #pragma unroll
            for (int nh = 0; nh < 4; nh++) {
                int n  = nh * 16 + (lane & 7) + ((lane >> 4) << 3);
                int ku = ((lane & 8) >> 3) + ku0;
                ldsm4(bf[nh], sB + n * 128 + ((ku ^ (n & 7)) << 4));
            }
            #pragma unroll
            for (int nt = 0; nt < 8; nt++)
                mma_f16(acc[nt], af[0], af[1], af[2], af[3],
                        bf[nt >> 1][(nt & 1) * 2], bf[nt >> 1][(nt & 1) * 2 + 1]);
        }
        __syncthreads();
    }

    // epilogue: write dout[b][t][a]
    const int m0 = w * 16 + (lane >> 2);
    #pragma unroll
    for (int nt = 0; nt < 8; nt++) {
        int a0 = nt * 8 + 2 * (lane & 3);
        float bv0 = __ldg(bout + a0), bv1 = __ldg(bout + a0 + 1);
        float* d0 = dout + (size_t)(b0 + m0) * SS * AA + tt * AA + a0;
        float* d1 = dout + (size_t)(b0 + m0 + 8) * SS * AA + tt * AA + a0;
        d0[0] = acc[nt][0] + bv0;
        d0[1] = acc[nt][1] + bv1;
        d1[0] = acc[nt][2] + bv0;
        d1[1] = acc[nt][3] + bv1;
    }
}

// ---------------- launch ----------------
extern "C" void kernel_launch(void* const* d_in, const int* in_sizes, int n_in,
                              void* d_out, int out_size)
{
    const float* observe  = (const float*)d_in[0];
    const float* obstacle = (const float*)d_in[1];
    const float* mask     = (const float*)d_in[2];
    const float* W1       = (const float*)d_in[3];
    const float* b1       = (const float*)d_in[4];
    const float* W2       = (const float*)d_in[5];
    const float* b2       = (const float*)d_in[6];
    const float* W_ih     = (const float*)d_in[7];
    const float* b_ih     = (const float*)d_in[8];
    const float* W_hh     = (const float*)d_in[9];
    const float* b_hh     = (const float*)d_in[10];
    const float* W_out    = (const float*)d_in[11];
    const float* b_out    = (const float*)d_in[12];
    float* out = (float*)d_out;

    cudaFuncSetAttribute(lstm_kernel, cudaFuncAttributeMaxDynamicSharedMemorySize, SMEM_BYTES);
    cudaFuncSetAttribute(finalout_kernel, cudaFuncAttributeMaxDynamicSharedMemorySize, FOUT_SMEM);

    bias_kernel<<<16, 256>>>(W2, b1, b2, b_ih, b_hh, W_ih, b_out);
    collapse_kernel<<<IN_D, 256>>>(W1, W2);
    wprep_kernel<<<64, 256>>>(W_ih, W_hh, W_out);
    wfin_kernel<<<16, 256>>>(W_out);
    mlp_kernel<<<SS * 16, 256>>>(observe, obstacle, mask);
    lstm_kernel<<<NCTA, 256, SMEM_BYTES>>>(0);
    finalout_kernel<<<SS * 2, 256, FOUT_SMEM>>>(b_out, out);
}

// round 13
// speedup vs baseline: 1.9795x; 1.0105x over previous
#include <cuda_runtime.h>
#include <cuda_fp16.h>
#include <math.h>
#include <stdint.h>

// Problem constants
#define BB    256
#define SS    128
#define IN_D  192
#define MLP_O 256
#define HH    1024
#define AA    64
#define K2    1280          // MLP_O + HH (o_prev folded away)
#define CK    64            // K per chunk
#define NCH   20            // K2/CK  (chunks 0..3 = mlp part, 4..19 = h part)
#define G4    4096
#define NCTA  128
#define NTHR  512           // lstm threads (16 warps)

// lstm smem geometry (halfs) — W persistent + per-quad swizzled A stages
#define W_HALFS  (NCH * 64 * CK)       // 81920 halfs = 160 KB
#define ASTG2_B  4096                  // bytes per quad stage (32 rows x 64 halfs)
#define NSTG     4
#define A_HALFS  (4 * NSTG * (ASTG2_B / 2))              // 32768 halfs = 64 KB
#define SMEM_BYTES ((W_HALFS + A_HALFS) * 2)             // 229376 B

// finalout smem: Wout image (16 chunks x 4096 halfs = 128 KB) + 2 H stages (16 KB each)
#define FW_HALFS  (16 * 64 * 64)                          // 65536 halfs = 128 KB
#define FSTG_B    16384                                   // 128 rows x 128 B
#define FOUT_SMEM (FW_HALFS * 2 + 2 * FSTG_B)             // 163840 B

// ---------------- device scratch ----------------
__device__ __align__(16) float g_WcT[IN_D * MLP_O];
__device__ float g_bc[MLP_O];
__device__ float g_bias0[G4];        // b_ih + b_hh             (t == 0)
__device__ float g_bias1[G4];        // + W_ihA @ bout          (t >= 1)
__device__ __align__(16) __half g_Wph[64 * W_HALFS];              // packed swizzled fp16 W
__device__ __align__(16) __half g_Wfin[FW_HALFS];                 // packed swizzled fp16 Wout
__device__ __align__(16) __half g_Ah[(size_t)(SS + 1) * BB * K2]; // [t][b][k] slabs fp16
__device__ unsigned g_cnt = 0;
__device__ unsigned g_gen = 0;

__device__ __forceinline__ uint32_t smem_u32(const void* p)
{
    uint32_t a;
    asm("{ .reg .u64 t; cvta.to.shared.u64 t, %1; cvt.u32.u64 %0, t; }" : "=r"(a) : "l"(p));
    return a;
}

__device__ __forceinline__ void cpasync16(uint32_t dst, const void* src)
{
    asm volatile("cp.async.cg.shared.global [%0], [%1], 16;" :: "r"(dst), "l"(src));
}
#define CP_COMMIT() asm volatile("cp.async.commit_group;")
#define CP_WAIT(N)  asm volatile("cp.async.wait_group %0;" :: "n"(N))

__device__ __forceinline__ void ldsm4(uint32_t r[4], uint32_t addr)
{
    asm volatile("ldmatrix.sync.aligned.m8n8.x4.shared.b16 {%0,%1,%2,%3}, [%4];"
                 : "=r"(r[0]), "=r"(r[1]), "=r"(r[2]), "=r"(r[3]) : "r"(addr));
}

__device__ __forceinline__ void mma_f16(float c[4],
                                        uint32_t a0, uint32_t a1, uint32_t a2, uint32_t a3,
                                        uint32_t b0, uint32_t b1)
{
    asm("mma.sync.aligned.m16n8k16.row.col.f32.f16.f16.f32 "
        "{%0,%1,%2,%3}, {%4,%5,%6,%7}, {%8,%9}, {%0,%1,%2,%3};"
        : "+f"(c[0]), "+f"(c[1]), "+f"(c[2]), "+f"(c[3])
        : "r"(a0), "r"(a1), "r"(a2), "r"(a3), "r"(b0), "r"(b1));
}

__device__ __forceinline__ float fast_sig(float x)
{
    return 1.f / (1.f + __expf(-x));
}
__device__ __forceinline__ float fast_tanh(float x)
{
    x = fminf(fmaxf(x, -15.f), 15.f);
    float e = __expf(2.f * x);
    return (e - 1.f) / (e + 1.f);
}

// ---------------- full grid barrier (init only) ----------------
__device__ __forceinline__ void grid_barrier(unsigned &gen)
{
    __syncthreads();
    if (threadIdx.x == 0) {
        __threadfence();
        unsigned ticket = atomicAdd(&g_cnt, 1u);
        if (ticket == NCTA - 1u) {
            g_cnt = 0u;
            __threadfence();
            atomicAdd(&g_gen, 1u);
        } else {
            while (*((volatile unsigned *)&g_gen) == gen) { }
            __threadfence();
        }
    }
    gen += 1u;
    __syncthreads();
}

// ---------------- kernel 0: biases ----------------
__global__ void bias_kernel(const float* __restrict__ W2, const float* __restrict__ b1,
                            const float* __restrict__ b2, const float* __restrict__ bih,
                            const float* __restrict__ bhh, const float* __restrict__ Wih,
                            const float* __restrict__ bout)
{
    int n = blockIdx.x * 256 + threadIdx.x;
    float base = bih[n] + bhh[n];
    float fold = 0.f;
    const float* wa = Wih + n * 320 + 256;
    #pragma unroll
    for (int a = 0; a < 64; a++) fold = fmaf(wa[a], bout[a], fold);
    g_bias0[n] = base;
    g_bias1[n] = base + fold;

    if (blockIdx.x == 0) {
        int tid = threadIdx.x;
        const float* w2r = W2 + tid * 1024;
        float acc = b2[tid];
        #pragma unroll 4
        for (int h = 0; h < 1024; h += 4) {
            float4 w = *(const float4*)(w2r + h);
            acc = fmaf(w.x, b1[h], acc);
            acc = fmaf(w.y, b1[h+1], acc);
            acc = fmaf(w.z, b1[h+2], acc);
            acc = fmaf(w.w, b1[h+3], acc);
        }
        g_bc[tid] = acc;
    }
}

// ---------------- kernel 1: collapse W2@W1 -> WcT[k][o] ----------------
__global__ void collapse_kernel(const float* __restrict__ W1, const float* __restrict__ W2)
{
    __shared__ float w1k[1024];
    int k = blockIdx.x;
    for (int h = threadIdx.x; h < 1024; h += 256) w1k[h] = W1[h * IN_D + k];
    __syncthreads();
    int o = threadIdx.x;
    const float* w2r = W2 + o * 1024;
    float acc = 0.f;
    #pragma unroll 4
    for (int h = 0; h < 1024; h += 4) {
        float4 w = *(const float4*)(w2r + h);
        acc = fmaf(w.x, w1k[h],   acc);
        acc = fmaf(w.y, w1k[h+1], acc);
        acc = fmaf(w.z, w1k[h+2], acc);
        acc = fmaf(w.w, w1k[h+3], acc);
    }
    g_WcT[k * MLP_O + o] = acc;
}

// ---------------- kernel 2: pack fused+folded weights (fp16, swizzled smem image) ----------------
__global__ void wprep_kernel(const float* __restrict__ Wih, const float* __restrict__ Whh,
                             const float* __restrict__ Wout)
{
    __shared__ float As[64 * 68];
    __shared__ float Wc[64 * 68];
    const int jb  = blockIdx.x;
    const int tid = threadIdx.x;
    __half* wp = g_Wph + (size_t)jb * W_HALFS;

    #pragma unroll
    for (int q = 0; q < 16; q++) {
        int idx = q * 256 + tid;
        int col = idx >> 6, a = idx & 63;
        int row = (col >> 4) * 1024 + jb * 16 + (col & 15);
        As[col * 68 + a] = Wih[row * 320 + 256 + a];
    }
    // part 1: k < 256
    #pragma unroll 4
    for (int q = 0; q < 64; q++) {
        int idx = q * 256 + tid;
        int col = idx >> 8, k = idx & 255;
        int row = (col >> 4) * 1024 + jb * 16 + (col & 15);
        int sw  = ((k >> 3) & 7) ^ (col & 7);
        wp[(k >> 6) * 4096 + col * 64 + sw * 8 + (k & 7)] = __float2half(Wih[row * 320 + k]);
    }
    __syncthreads();

    const int col = tid & 63;
    const int hq  = tid >> 6;
    const int row = (col >> 4) * 1024 + jb * 16 + (col & 15);
    for (int hc = 0; hc < 16; hc++) {
        #pragma unroll 4
        for (int q = 0; q < 16; q++) {
            int idx = q * 256 + tid;
            int a = idx >> 6, h = idx & 63;
            Wc[a * 68 + h] = Wout[a * 1024 + hc * 64 + h];
        }
        __syncthreads();
        #pragma unroll 2
        for (int i = 0; i < 16; i++) {
            int h  = hq * 16 + i;
            int hh = hc * 64 + h;
            float fold = 0.f;
            #pragma unroll 8
            for (int a = 0; a < 64; a++)
                fold = fmaf(As[col * 68 + a], Wc[a * 68 + h], fold);
            float val = Whh[row * 1024 + hh] + fold;
            int k = 256 + hh;
            int sw = ((k >> 3) & 7) ^ (col & 7);
            wp[(k >> 6) * 4096 + col * 64 + sw * 8 + (k & 7)] = __float2half(val);
        }
        __syncthreads();
    }
}

// ---------------- kernel 2b: pack Wout fp16 swizzled image for finalout ----------------
__global__ void wfin_kernel(const float* __restrict__ Wout)
{
    const int cc  = blockIdx.x;          // 0..15 (K chunk)
    const int tid = threadIdx.x;
    __half* wp = g_Wfin + cc * 4096;
    #pragma unroll
    for (int q = 0; q < 16; q++) {
        int idx = q * 256 + tid;         // 0..4095
        int n = idx >> 6, kk = idx & 63;
        int sw = ((kk >> 3) & 7) ^ (n & 7);
        wp[n * 64 + sw * 8 + (kk & 7)] = __float2half(Wout[n * 1024 + cc * 64 + kk]);
    }
}

// ---------------- kernel 3: mlp -> g_Ah[s][b][k] (fp16) ----------------
__global__ void mlp_kernel(const float* __restrict__ observe,
                           const float* __restrict__ obstacle,
                           const float* __restrict__ mask)
{
    __shared__ float xs[16 * IN_D];
    __shared__ __half hs[16 * 272];
    const int tid = threadIdx.x;
    const int s   = blockIdx.x >> 4;
    const int b0  = (blockIdx.x & 15) * 16;
    for (int idx = tid; idx < 16 * IN_D; idx += 256) {
        int i = idx / IN_D, k = idx - i * IN_D;
        int p = (b0 + i) * 128 + s;
        float v;
        if (k < 64) v = observe[p * 64 + k];
        else {
            int kk = k - 64;
            v = obstacle[p * 128 + kk] * mask[p * 8 + (kk >> 4)];
        }
        xs[i * IN_D + k] = v;
    }
    __syncthreads();

    float acc[16];
    #pragma unroll
    for (int i = 0; i < 16; i++) acc[i] = 0.f;
    #pragma unroll 4
    for (int k = 0; k < IN_D; k++) {
        float w = g_WcT[k * MLP_O + tid];
        #pragma unroll
        for (int i = 0; i < 16; i++)
            acc[i] = fmaf(xs[i * IN_D + k], w, acc[i]);
    }
    float bcv = g_bc[tid];
    #pragma unroll
    for (int i = 0; i < 16; i++)
        hs[i * 272 + tid] = __float2half(fmaxf(acc[i] + bcv, 0.f));
    __syncthreads();
    int i2 = tid >> 4, seg = tid & 15;
    uint4 v0 = *(uint4*)&hs[i2 * 272 + seg * 16];
    uint4 v1 = *(uint4*)&hs[i2 * 272 + seg * 16 + 8];
    __half* dst = g_Ah + (size_t)s * BB * K2 + (size_t)(b0 + i2) * K2 + seg * 16;
    *(uint4*)dst = v0;
    *(uint4*)(dst + 8) = v1;
}

// ---------------- kernel 4: persistent LSTM (16 warps, quad-shared A stages) ----------------
__global__ void __launch_bounds__(NTHR, 1)
lstm_kernel(int dummy)
{
    extern __shared__ __half smh[];
    float* sg = (float*)(smh + W_HALFS);     // epilogue alias of A stage region
    __shared__ float sbias[2][64];

    const int tid  = threadIdx.x;
    const int cta  = blockIdx.x;
    const int mh   = cta & 1;                // batch half
    const int jb   = cta >> 1;               // j block (16 j's)
    const int j0   = jb * 16;
    const int lane = tid & 31;
    const int w    = tid >> 5;               // 0..15
    const int wm   = w & 3;                  // M quarter (32 rows) == quad id
    const int wn   = w >> 2;                 // N quarter (16 cols), 0..3
    unsigned gen = *((volatile unsigned*)&g_gen);

    const uint32_t sbase = smem_u32(smh);
    const uint32_t wbase = sbase;
    const uint32_t abase = sbase + W_HALFS * 2;

    // ---- load persistent W (swizzled image, straight copy) ----
    {
        const __half* src = g_Wph + (size_t)jb * W_HALFS;
        for (int u = tid; u < W_HALFS / 8; u += NTHR)
            cpasync16(wbase + u * 16, src + (size_t)u * 8);
        CP_COMMIT();
    }

    // ---- init: slab0 h-part = 0, sbias; c lives in registers ----
    const int gt = cta * NTHR + tid;
    for (int i = gt; i < (HH * BB) / 2; i += NCTA * NTHR) {
        int b = i >> 9, off = (i & 511) * 2;
        *(uint32_t*)&g_Ah[(size_t)b * K2 + 256 + off] = 0u;
    }
    if (tid < 64) {
        int gate = tid >> 4, jl = tid & 15;
        sbias[0][tid] = g_bias0[gate * 1024 + j0 + jl];
        sbias[1][tid] = g_bias1[gate * 1024 + j0 + jl];
    }
    float c_reg[4];
    #pragma unroll
    for (int q = 0; q < 4; q++) c_reg[q] = 0.f;
    CP_WAIT(0);
    grid_barrier(gen);

    // quad barrier: warps {wm, wm+4, wm+8, wm+12}, 128 threads, named barrier wm+1
    #define BAR_QUAD() asm volatile("bar.sync %0, %1;" :: "r"(wm + 1), "r"(128) : "memory")

    // quad A prefetch: 4 warps of the quad split the 4KB sub-tile (2 cp.async/lane)
    auto prefA = [&](const __half* Asl, int cc) {
        uint32_t sd = abase + (wm * NSTG + (cc & 3)) * ASTG2_B;
        const __half* src = Asl + (size_t)(wm * 32) * K2 + cc * CK;
        #pragma unroll
        for (int i = 0; i < 2; i++) {
            int idx = i * 128 + wn * 32 + lane;     // 0..255 unit id
            int r = idx >> 3, u = idx & 7;
            cpasync16(sd + r * 128 + ((u ^ (r & 7)) << 4), src + (size_t)r * K2 + u * 8);
        }
        CP_COMMIT();
    };

    // one K=64 chunk: quad stage (cc&3) + persistent W chunk cc; warp tile 32x16
    auto do_chunk = [&](int cc, float (&acc)[2][2][4]) {
        uint32_t sA = abase + (wm * NSTG + (cc & 3)) * ASTG2_B;
        uint32_t sB = wbase + cc * 8192;
        #pragma unroll
        for (int ks = 0; ks < 4; ks++) {
            const int ku0 = ks * 2;
            uint32_t af[2][4], bf[4];
            #pragma unroll
            for (int mt = 0; mt < 2; mt++) {
                int lr = mt * 16 + (lane & 15);     // local row in quad tile
                int ku = (lane >> 4) + ku0;
                ldsm4(af[mt], sA + lr * 128 + ((ku ^ (lr & 7)) << 4));
            }
            {
                int n  = wn * 16 + (lane & 7) + ((lane >> 4) << 3);
                int ku = ((lane & 8) >> 3) + ku0;
                ldsm4(bf, sB + n * 128 + ((ku ^ (n & 7)) << 4));
            }
            #pragma unroll
            for (int mt = 0; mt < 2; mt++)
                #pragma unroll
                for (int nt = 0; nt < 2; nt++)
                    mma_f16(acc[mt][nt],
                            af[mt][0], af[mt][1], af[mt][2], af[mt][3],
                            bf[nt * 2], bf[nt * 2 + 1]);
        }
    };

    // prime: slab0 chunks 0,1,2 (mlp part, no cross-CTA dependency)
    prefA(g_Ah + (size_t)mh * 128 * K2, 0);
    prefA(g_Ah + (size_t)mh * 128 * K2, 1);
    prefA(g_Ah + (size_t)mh * 128 * K2, 2);

    for (int t = 0; t < SS; ++t) {
        const __half* Asl = g_Ah + (size_t)t * BB * K2 + (size_t)mh * 128 * K2;

        float acc[2][2][4];
        #pragma unroll
        for (int mt = 0; mt < 2; mt++)
            #pragma unroll
            for (int nt = 0; nt < 2; nt++)
                #pragma unroll
                for (int r = 0; r < 4; r++) acc[mt][nt][r] = 0.f;

        // ---- pre-wait region: mlp chunks 0..3 (quad-local pipeline) ----
        for (int cc = 0; cc < 4; cc++) {
            if (cc == 0) prefA(Asl, 3);          // last mlp chunk
            if      (cc == 0) CP_WAIT(3);
            else if (cc == 1) CP_WAIT(2);
            else if (cc == 2) CP_WAIT(1);
            else              CP_WAIT(0);
            BAR_QUAD();
            do_chunk(cc, acc);
        }

        // ---- global barrier wait (arrive happened at end of previous step) ----
        if (t > 0) {
            if (tid == 0) {
                while (*((volatile unsigned*)&g_gen) == gen) { }
                __threadfence();
            }
            gen += 1u;
        }
        __syncthreads();

        // ---- h chunks 4..19 (quad-local pipeline, distance-3 prefetch) ----
        prefA(Asl, 4);
        prefA(Asl, 5);
        prefA(Asl, 6);
        for (int cc = 4; cc < NCH; cc++) {
            if (cc + 3 < NCH) prefA(Asl, cc + 3);
            if      (cc <  NCH - 3) CP_WAIT(3);
            else if (cc == NCH - 3) CP_WAIT(2);
            else if (cc == NCH - 2) CP_WAIT(1);
            else                    CP_WAIT(0);
            BAR_QUAD();
            do_chunk(cc, acc);
        }
        __syncthreads();   // all quads done -> stage region reusable as sg

        // ---- epilogue: acc -> sg[col][m] ----
        #pragma unroll
        for (int mt = 0; mt < 2; mt++) {
            int m0 = wm * 32 + mt * 16 + (lane >> 2);
            #pragma unroll
            for (int nt = 0; nt < 2; nt++) {
                int c0 = wn * 16 + nt * 8 + 2 * (lane & 3);
                sg[c0 * 132 + m0]           = acc[mt][nt][0];
                sg[(c0 + 1) * 132 + m0]     = acc[mt][nt][1];
                sg[c0 * 132 + m0 + 8]       = acc[mt][nt][2];
                sg[(c0 + 1) * 132 + m0 + 8] = acc[mt][nt][3];
            }
        }
        __syncthreads();

        // ---- cell update (c in registers; thread = batch row x 4 j's) ----
        {
            const int b  = tid & 127;
            const int js = (tid >> 7) * 4;       // 0,4,8,12
            const float* bs = sbias[t > 0 ? 1 : 0];
            __align__(8) __half hbuf[4];
            #pragma unroll
            for (int q = 0; q < 4; q++) {
                int jl = js + q;
                float iv = fast_sig (sg[jl * 132 + b]        + bs[jl]);
                float fv = fast_sig (sg[(16 + jl) * 132 + b] + bs[16 + jl]);
                float gv = fast_tanh(sg[(32 + jl) * 132 + b] + bs[32 + jl]);
                float ov = fast_sig (sg[(48 + jl) * 132 + b] + bs[48 + jl]);
                float cnew = fmaf(fv, c_reg[q], iv * gv);
                c_reg[q] = cnew;
                hbuf[q] = __float2half(ov * fast_tanh(cnew));
            }
            __half* hd = g_Ah + (size_t)(t + 1) * BB * K2
                       + (size_t)(mh * 128 + b) * K2 + 256 + j0 + js;
            *(uint2*)hd = *(uint2*)hbuf;
        }
        __syncthreads();   // sg reads done before stages reused

        // ---- split-barrier arrive + prime next-step mlp chunks ----
        if (t + 1 < SS) {
            if (tid == 0) {
                __threadfence();
                unsigned ticket = atomicAdd(&g_cnt, 1u);
                if (ticket == NCTA - 1u) {
                    g_cnt = 0u;
                    __threadfence();
                    atomicAdd(&g_gen, 1u);
                }
            }
            const __half* AslN = Asl + (size_t)BB * K2;
            prefA(AslN, 0);
            prefA(AslN, 1);
            prefA(AslN, 2);
        }
    }
    #undef BAR_QUAD
}

// ---------------- kernel 5: out[b][t][a] = h_t @ Wout^T + bout (fp16 mma) ----------------
__global__ void __launch_bounds__(256, 1)
finalout_kernel(const float* __restrict__ bout, float* __restrict__ dout)
{
    extern __shared__ __half fsm[];
    const int tid  = threadIdx.x;
    const int lane = tid & 31;
    const int w    = tid >> 5;               // warp -> rows [w*16, w*16+16)
    const int tt   = blockIdx.x >> 1;
    const int b0   = (blockIdx.x & 1) * 128;

    const uint32_t sbase = smem_u32(fsm);
    const uint32_t wbase = sbase;                       // Wout image: 16 chunks x 8192 B
    const uint32_t hbase = sbase + FW_HALFS * 2;        // 2 H stages x 16384 B

    const __half* hsl = g_Ah + (size_t)(tt + 1) * BB * K2 + (size_t)b0 * K2 + 256;

    // load Wout image (128 KB)
    for (int u = tid; u < FW_HALFS / 8; u += 256)
        cpasync16(wbase + u * 16, g_Wfin + (size_t)u * 8);

    // prefetch H chunk 0
    auto prefH = [&](int cc) {
        uint32_t sd = hbase + (cc & 1) * FSTG_B;
        #pragma unroll
        for (int i = 0; i < 4; i++) {
            int idx = i * 256 + tid;         // 0..1023 units (128 rows x 8)
            int r = idx >> 3, u = idx & 7;
            cpasync16(sd + r * 128 + ((u ^ (r & 7)) << 4),
                      hsl + (size_t)r * K2 + cc * 64 + u * 8);
        }
        CP_COMMIT();
    };
    prefH(0);

    float acc[8][4];
    #pragma unroll
    for (int nt = 0; nt < 8; nt++)
        #pragma unroll
        for (int r = 0; r < 4; r++) acc[nt][r] = 0.f;

    for (int cc = 0; cc < 16; cc++) {
        if (cc + 1 < 16) { prefH(cc + 1); CP_WAIT(1); }
        else             { CP_WAIT(0); }
        __syncthreads();
        uint32_t sA = hbase + (cc & 1) * FSTG_B;
        uint32_t sB = wbase + cc * 8192;
        #pragma unroll
        for (int ks = 0; ks < 4; ks++) {
            const int ku0 = ks * 2;
            uint32_t af[4], bf[4][4];
            {
                int lr = w * 16 + (lane & 15);
                int ku = (lane >> 4) + ku0;
                ldsm4(af, sA + lr * 128 + ((ku ^ (lr & 7)) << 4));
            }
            #pragma unroll
            for (int nh = 0; nh < 4; nh++) {
                int n  = nh * 16 + (lane & 7) + ((lane >> 4) << 3);
                int ku = ((lane & 8) >> 3) + ku0;
                ldsm4(bf[nh], sB + n * 128 + ((ku ^ (n & 7)) << 4));
            }
            #pragma unroll
            for (int nt = 0; nt < 8; nt++)
                mma_f16(acc[nt], af[0], af[1], af[2], af[3],
                        bf[nt >> 1][(nt & 1) * 2], bf[nt >> 1][(nt & 1) * 2 + 1]);
        }
        __syncthreads();
    }

    // epilogue: write dout[b][t][a]
    const int m0 = w * 16 + (lane >> 2);
    #pragma unroll
    for (int nt = 0; nt < 8; nt++) {
        int a0 = nt * 8 + 2 * (lane & 3);
        float bv0 = __ldg(bout + a0), bv1 = __ldg(bout + a0 + 1);
        float* d0 = dout + (size_t)(b0 + m0) * SS * AA + tt * AA + a0;
        float* d1 = dout + (size_t)(b0 + m0 + 8) * SS * AA + tt * AA + a0;
        d0[0] = acc[nt][0] + bv0;
        d0[1] = acc[nt][1] + bv1;
        d1[0] = acc[nt][2] + bv0;
        d1[1] = acc[nt][3] + bv1;
    }
}

// ---------------- launch ----------------
extern "C" void kernel_launch(void* const* d_in, const int* in_sizes, int n_in,
                              void* d_out, int out_size)
{
    const float* observe  = (const float*)d_in[0];
    const float* obstacle = (const float*)d_in[1];
    const float* mask     = (const float*)d_in[2];
    const float* W1       = (const float*)d_in[3];
    const float* b1       = (const float*)d_in[4];
    const float* W2       = (const float*)d_in[5];
    const float* b2       = (const float*)d_in[6];
    const float* W_ih     = (const float*)d_in[7];
    const float* b_ih     = (const float*)d_in[8];
    const float* W_hh     = (const float*)d_in[9];
    const float* b_hh     = (const float*)d_in[10];
    const float* W_out    = (const float*)d_in[11];
    const float* b_out    = (const float*)d_in[12];
    float* out = (float*)d_out;

    cudaFuncSetAttribute(lstm_kernel, cudaFuncAttributeMaxDynamicSharedMemorySize, SMEM_BYTES);
    cudaFuncSetAttribute(finalout_kernel, cudaFuncAttributeMaxDynamicSharedMemorySize, FOUT_SMEM);

    bias_kernel<<<16, 256>>>(W2, b1, b2, b_ih, b_hh, W_ih, b_out);
    collapse_kernel<<<IN_D, 256>>>(W1, W2);
    wprep_kernel<<<64, 256>>>(W_ih, W_hh, W_out);
    wfin_kernel<<<16, 256>>>(W_out);
    mlp_kernel<<<SS * 16, 256>>>(observe, obstacle, mask);
    lstm_kernel<<<NCTA, NTHR, SMEM_BYTES>>>(0);
    finalout_kernel<<<SS * 2, 256, FOUT_SMEM>>>(b_out, out);
}

// round 15
// speedup vs baseline: 1.9837x; 1.0021x over previous
#include <cuda_runtime.h>
#include <cuda_fp16.h>
#include <math.h>
#include <stdint.h>

// Problem constants
#define BB    256
#define SS    128
#define IN_D  192
#define MLP_O 256
#define HH    1024
#define AA    64
#define K2    1280          // MLP_O + HH (o_prev folded away)
#define CK    64            // K per chunk
#define NCH   20            // K2/CK  (chunks 0..3 = mlp part, 4..19 = h part)
#define G4    4096
#define NCTA  128
#define NTHR  512           // lstm threads (16 warps)

// lstm smem geometry (halfs) — W persistent + per-quad swizzled A stages
#define W_HALFS  (NCH * 64 * CK)       // 81920 halfs = 160 KB
#define ASTG2_B  4096                  // bytes per quad stage (32 rows x 64 halfs)
#define NSTG     4
#define A_HALFS  (4 * NSTG * (ASTG2_B / 2))              // 32768 halfs = 64 KB
#define SMEM_BYTES ((W_HALFS + A_HALFS) * 2)             // 229376 B

// finalout smem: Wout image (16 chunks x 4096 halfs = 128 KB) + 2 H stages (16 KB each)
#define FW_HALFS  (16 * 64 * 64)                          // 65536 halfs = 128 KB
#define FSTG_B    16384                                   // 128 rows x 128 B
#define FOUT_SMEM (FW_HALFS * 2 + 2 * FSTG_B)             // 163840 B

// ---------------- device scratch ----------------
__device__ __align__(16) float g_WcT[IN_D * MLP_O];
__device__ float g_bc[MLP_O];
__device__ float g_bias0[G4];        // b_ih + b_hh             (t == 0)
__device__ float g_bias1[G4];        // + W_ihA @ bout          (t >= 1)
__device__ __align__(16) __half g_Wph[64 * W_HALFS];              // packed swizzled fp16 W
__device__ __align__(16) __half g_Wfin[FW_HALFS];                 // packed swizzled fp16 Wout
__device__ __align__(16) __half g_Ah[(size_t)(SS + 1) * BB * K2]; // [t][b][k] slabs fp16
__device__ unsigned g_cnt = 0;
__device__ unsigned g_gen = 0;
// tree barrier state (padded: one 128B line per counter)
__device__ unsigned g_leafp[16 * 32];
__device__ unsigned g_relp[16 * 32];
__device__ unsigned g_root = 0;

__device__ __forceinline__ uint32_t smem_u32(const void* p)
{
    uint32_t a;
    asm("{ .reg .u64 t; cvta.to.shared.u64 t, %1; cvt.u32.u64 %0, t; }" : "=r"(a) : "l"(p));
    return a;
}

__device__ __forceinline__ void cpasync16(uint32_t dst, const void* src)
{
    asm volatile("cp.async.cg.shared.global [%0], [%1], 16;" :: "r"(dst), "l"(src));
}
#define CP_COMMIT() asm volatile("cp.async.commit_group;")
#define CP_WAIT(N)  asm volatile("cp.async.wait_group %0;" :: "n"(N))

__device__ __forceinline__ void ldsm4(uint32_t r[4], uint32_t addr)
{
    asm volatile("ldmatrix.sync.aligned.m8n8.x4.shared.b16 {%0,%1,%2,%3}, [%4];"
                 : "=r"(r[0]), "=r"(r[1]), "=r"(r[2]), "=r"(r[3]) : "r"(addr));
}

__device__ __forceinline__ void mma_f16(float c[4],
                                        uint32_t a0, uint32_t a1, uint32_t a2, uint32_t a3,
                                        uint32_t b0, uint32_t b1)
{
    asm("mma.sync.aligned.m16n8k16.row.col.f32.f16.f16.f32 "
        "{%0,%1,%2,%3}, {%4,%5,%6,%7}, {%8,%9}, {%0,%1,%2,%3};"
        : "+f"(c[0]), "+f"(c[1]), "+f"(c[2]), "+f"(c[3])
        : "r"(a0), "r"(a1), "r"(a2), "r"(a3), "r"(b0), "r"(b1));
}

__device__ __forceinline__ float fast_sig(float x)
{
    return 1.f / (1.f + __expf(-x));
}
__device__ __forceinline__ float fast_tanh(float x)
{
    x = fminf(fmaxf(x, -15.f), 15.f);
    float e = __expf(2.f * x);
    return (e - 1.f) / (e + 1.f);
}

// ---------------- full grid barrier (init only) ----------------
__device__ __forceinline__ void grid_barrier(unsigned &gen)
{
    __syncthreads();
    if (threadIdx.x == 0) {
        __threadfence();
        unsigned ticket = atomicAdd(&g_cnt, 1u);
        if (ticket == NCTA - 1u) {
            g_cnt = 0u;
            __threadfence();
            atomicAdd(&g_gen, 1u);
        } else {
            while (*((volatile unsigned *)&g_gen) == gen) { }
            __threadfence();
        }
    }
    gen += 1u;
    __syncthreads();
}

// ---------------- kernel 0: biases ----------------
__global__ void bias_kernel(const float* __restrict__ W2, const float* __restrict__ b1,
                            const float* __restrict__ b2, const float* __restrict__ bih,
                            const float* __restrict__ bhh, const float* __restrict__ Wih,
                            const float* __restrict__ bout)
{
    int n = blockIdx.x * 256 + threadIdx.x;
    float base = bih[n] + bhh[n];
    float fold = 0.f;
    const float* wa = Wih + n * 320 + 256;
    #pragma unroll
    for (int a = 0; a < 64; a++) fold = fmaf(wa[a], bout[a], fold);
    g_bias0[n] = base;
    g_bias1[n] = base + fold;

    if (blockIdx.x == 0) {
        int tid = threadIdx.x;
        const float* w2r = W2 + tid * 1024;
        float acc = b2[tid];
        #pragma unroll 4
        for (int h = 0; h < 1024; h += 4) {
            float4 w = *(const float4*)(w2r + h);
            acc = fmaf(w.x, b1[h], acc);
            acc = fmaf(w.y, b1[h+1], acc);
            acc = fmaf(w.z, b1[h+2], acc);
            acc = fmaf(w.w, b1[h+3], acc);
        }
        g_bc[tid] = acc;
    }
}

// ---------------- kernel 1: collapse W2@W1 -> WcT[k][o] ----------------
__global__ void collapse_kernel(const float* __restrict__ W1, const float* __restrict__ W2)
{
    __shared__ float w1k[1024];
    int k = blockIdx.x;
    for (int h = threadIdx.x; h < 1024; h += 256) w1k[h] = W1[h * IN_D + k];
    __syncthreads();
    int o = threadIdx.x;
    const float* w2r = W2 + o * 1024;
    float acc = 0.f;
    #pragma unroll 4
    for (int h = 0; h < 1024; h += 4) {
        float4 w = *(const float4*)(w2r + h);
        acc = fmaf(w.x, w1k[h],   acc);
        acc = fmaf(w.y, w1k[h+1], acc);
        acc = fmaf(w.z, w1k[h+2], acc);
        acc = fmaf(w.w, w1k[h+3], acc);
    }
    g_WcT[k * MLP_O + o] = acc;
}

// ---------------- kernel 2: pack fused+folded weights (fp16, swizzled smem image) ----------------
__global__ void wprep_kernel(const float* __restrict__ Wih, const float* __restrict__ Whh,
                             const float* __restrict__ Wout)
{
    __shared__ float As[64 * 68];
    __shared__ float Wc[64 * 68];
    const int jb  = blockIdx.x;
    const int tid = threadIdx.x;
    __half* wp = g_Wph + (size_t)jb * W_HALFS;

    #pragma unroll
    for (int q = 0; q < 16; q++) {
        int idx = q * 256 + tid;
        int col = idx >> 6, a = idx & 63;
        int row = (col >> 4) * 1024 + jb * 16 + (col & 15);
        As[col * 68 + a] = Wih[row * 320 + 256 + a];
    }
    // part 1: k < 256
    #pragma unroll 4
    for (int q = 0; q < 64; q++) {
        int idx = q * 256 + tid;
        int col = idx >> 8, k = idx & 255;
        int row = (col >> 4) * 1024 + jb * 16 + (col & 15);
        int sw  = ((k >> 3) & 7) ^ (col & 7);
        wp[(k >> 6) * 4096 + col * 64 + sw * 8 + (k & 7)] = __float2half(Wih[row * 320 + k]);
    }
    __syncthreads();

    const int col = tid & 63;
    const int hq  = tid >> 6;
    const int row = (col >> 4) * 1024 + jb * 16 + (col & 15);
    for (int hc = 0; hc < 16; hc++) {
        #pragma unroll 4
        for (int q = 0; q < 16; q++) {
            int idx = q * 256 + tid;
            int a = idx >> 6, h = idx & 63;
            Wc[a * 68 + h] = Wout[a * 1024 + hc * 64 + h];
        }
        __syncthreads();
        #pragma unroll 2
        for (int i = 0; i < 16; i++) {
            int h  = hq * 16 + i;
            int hh = hc * 64 + h;
            float fold = 0.f;
            #pragma unroll 8
            for (int a = 0; a < 64; a++)
                fold = fmaf(As[col * 68 + a], Wc[a * 68 + h], fold);
            float val = Whh[row * 1024 + hh] + fold;
            int k = 256 + hh;
            int sw = ((k >> 3) & 7) ^ (col & 7);
            wp[(k >> 6) * 4096 + col * 64 + sw * 8 + (k & 7)] = __float2half(val);
        }
        __syncthreads();
    }
}

// ---------------- kernel 2b: pack Wout fp16 swizzled image for finalout ----------------
__global__ void wfin_kernel(const float* __restrict__ Wout)
{
    const int cc  = blockIdx.x;          // 0..15 (K chunk)
    const int tid = threadIdx.x;
    __half* wp = g_Wfin + cc * 4096;
    #pragma unroll
    for (int q = 0; q < 16; q++) {
        int idx = q * 256 + tid;         // 0..4095
        int n = idx >> 6, kk = idx & 63;
        int sw = ((kk >> 3) & 7) ^ (n & 7);
        wp[n * 64 + sw * 8 + (kk & 7)] = __float2half(Wout[n * 1024 + cc * 64 + kk]);
    }
}

// ---------------- kernel 3: mlp -> g_Ah[s][b][k] (fp16) ----------------
__global__ void mlp_kernel(const float* __restrict__ observe,
                           const float* __restrict__ obstacle,
                           const float* __restrict__ mask)
{
    __shared__ float xs[16 * IN_D];
    __shared__ __half hs[16 * 272];
    const int tid = threadIdx.x;
    const int s   = blockIdx.x >> 4;
    const int b0  = (blockIdx.x & 15) * 16;
    for (int idx = tid; idx < 16 * IN_D; idx += 256) {
        int i = idx / IN_D, k = idx - i * IN_D;
        int p = (b0 + i) * 128 + s;
        float v;
        if (k < 64) v = observe[p * 64 + k];
        else {
            int kk = k - 64;
            v = obstacle[p * 128 + kk] * mask[p * 8 + (kk >> 4)];
        }
        xs[i * IN_D + k] = v;
    }
    __syncthreads();

    float acc[16];
    #pragma unroll
    for (int i = 0; i < 16; i++) acc[i] = 0.f;
    #pragma unroll 4
    for (int k = 0; k < IN_D; k++) {
        float w = g_WcT[k * MLP_O + tid];
        #pragma unroll
        for (int i = 0; i < 16; i++)
            acc[i] = fmaf(xs[i * IN_D + k], w, acc[i]);
    }
    float bcv = g_bc[tid];
    #pragma unroll
    for (int i = 0; i < 16; i++)
        hs[i * 272 + tid] = __float2half(fmaxf(acc[i] + bcv, 0.f));
    __syncthreads();
    int i2 = tid >> 4, seg = tid & 15;
    uint4 v0 = *(uint4*)&hs[i2 * 272 + seg * 16];
    uint4 v1 = *(uint4*)&hs[i2 * 272 + seg * 16 + 8];
    __half* dst = g_Ah + (size_t)s * BB * K2 + (size_t)(b0 + i2) * K2 + seg * 16;
    *(uint4*)dst = v0;
    *(uint4*)(dst + 8) = v1;
}

// ---------------- kernel 4: persistent LSTM (16 warps, tree barrier) ----------------
__global__ void __launch_bounds__(NTHR, 1)
lstm_kernel(int dummy)
{
    extern __shared__ __half smh[];
    float* sg = (float*)(smh + W_HALFS);     // epilogue alias of A stage region
    __shared__ float sbias[2][64];

    const int tid  = threadIdx.x;
    const int cta  = blockIdx.x;
    const int mh   = cta & 1;                // batch half
    const int jb   = cta >> 1;               // j block (16 j's)
    const int j0   = jb * 16;
    const int lane = tid & 31;
    const int w    = tid >> 5;               // 0..15
    const int wm   = w & 3;                  // M quarter (32 rows) == quad id
    const int wn   = w >> 2;                 // N quarter (16 cols), 0..3
    const int grp  = cta >> 3;               // tree-barrier leaf/release group
    unsigned gen = *((volatile unsigned*)&g_gen);

    const uint32_t sbase = smem_u32(smh);
    const uint32_t wbase = sbase;
    const uint32_t abase = sbase + W_HALFS * 2;

    // ---- load persistent W (swizzled image, straight copy) ----
    {
        const __half* src = g_Wph + (size_t)jb * W_HALFS;
        for (int u = tid; u < W_HALFS / 8; u += NTHR)
            cpasync16(wbase + u * 16, src + (size_t)u * 8);
        CP_COMMIT();
    }

    // ---- init: slab0 h-part = 0, sbias, tree counters; c in registers ----
    const int gt = cta * NTHR + tid;
    for (int i = gt; i < (HH * BB) / 2; i += NCTA * NTHR) {
        int b = i >> 9, off = (i & 511) * 2;
        *(uint32_t*)&g_Ah[(size_t)b * K2 + 256 + off] = 0u;
    }
    if (gt < 16 * 32) { g_leafp[gt] = 0u; g_relp[gt] = 0u; }
    if (gt == 16 * 32) g_root = 0u;
    if (tid < 64) {
        int gate = tid >> 4, jl = tid & 15;
        sbias[0][tid] = g_bias0[gate * 1024 + j0 + jl];
        sbias[1][tid] = g_bias1[gate * 1024 + j0 + jl];
    }
    float c_reg[4];
    #pragma unroll
    for (int q = 0; q < 4; q++) c_reg[q] = 0.f;
    CP_WAIT(0);
    grid_barrier(gen);     // replay-safe init barrier; tree counters now valid

    // quad barrier: warps {wm, wm+4, wm+8, wm+12}, 128 threads, named barrier wm+1
    #define BAR_QUAD() asm volatile("bar.sync %0, %1;" :: "r"(wm + 1), "r"(128) : "memory")

    // quad A prefetch: 4 warps of the quad split the 4KB sub-tile (2 cp.async/lane)
    auto prefA = [&](const __half* Asl, int cc) {
        uint32_t sd = abase + (wm * NSTG + (cc & 3)) * ASTG2_B;
        const __half* src = Asl + (size_t)(wm * 32) * K2 + cc * CK;
        #pragma unroll
        for (int i = 0; i < 2; i++) {
            int idx = i * 128 + wn * 32 + lane;     // 0..255 unit id
            int r = idx >> 3, u = idx & 7;
            cpasync16(sd + r * 128 + ((u ^ (r & 7)) << 4), src + (size_t)r * K2 + u * 8);
        }
        CP_COMMIT();
    };

    // one K=64 chunk: quad stage (cc&3) + persistent W chunk cc; warp tile 32x16
    auto do_chunk = [&](int cc, float (&acc)[2][2][4]) {
        uint32_t sA = abase + (wm * NSTG + (cc & 3)) * ASTG2_B;
        uint32_t sB = wbase + cc * 8192;
        #pragma unroll
        for (int ks = 0; ks < 4; ks++) {
            const int ku0 = ks * 2;
            uint32_t af[2][4], bf[4];
            #pragma unroll
            for (int mt = 0; mt < 2; mt++) {
                int lr = mt * 16 + (lane & 15);     // local row in quad tile
                int ku = (lane >> 4) + ku0;
                ldsm4(af[mt], sA + lr * 128 + ((ku ^ (lr & 7)) << 4));
            }
            {
                int n  = wn * 16 + (lane & 7) + ((lane >> 4) << 3);
                int ku = ((lane & 8) >> 3) + ku0;
                ldsm4(bf, sB + n * 128 + ((ku ^ (n & 7)) << 4));
            }
            #pragma unroll
            for (int mt = 0; mt < 2; mt++)
                #pragma unroll
                for (int nt = 0; nt < 2; nt++)
                    mma_f16(acc[mt][nt],
                            af[mt][0], af[mt][1], af[mt][2], af[mt][3],
                            bf[nt * 2], bf[nt * 2 + 1]);
        }
    };

    // prime: slab0 chunks 0,1,2 (mlp part, no cross-CTA dependency)
    prefA(g_Ah + (size_t)mh * 128 * K2, 0);
    prefA(g_Ah + (size_t)mh * 128 * K2, 1);
    prefA(g_Ah + (size_t)mh * 128 * K2, 2);

    for (int t = 0; t < SS; ++t) {
        const __half* Asl = g_Ah + (size_t)t * BB * K2 + (size_t)mh * 128 * K2;

        float acc[2][2][4];
        #pragma unroll
        for (int mt = 0; mt < 2; mt++)
            #pragma unroll
            for (int nt = 0; nt < 2; nt++)
                #pragma unroll
                for (int r = 0; r < 4; r++) acc[mt][nt][r] = 0.f;

        // ---- pre-wait region: mlp chunks 0..3 (quad-local pipeline) ----
        for (int cc = 0; cc < 4; cc++) {
            if (cc == 0) prefA(Asl, 3);          // last mlp chunk
            if      (cc == 0) CP_WAIT(3);
            else if (cc == 1) CP_WAIT(2);
            else if (cc == 2) CP_WAIT(1);
            else              CP_WAIT(0);
            BAR_QUAD();
            do_chunk(cc, acc);
        }

        // ---- tree-barrier wait (arrive happened at end of previous step) ----
        if (t > 0) {
            if (tid == 0) {
                const volatile unsigned* rl = &g_relp[grp * 32];
                while (*rl < (unsigned)t) { }
                __threadfence();
            }
        }
        __syncthreads();

        // ---- h chunks 4..19 (quad-local pipeline, distance-3 prefetch) ----
        prefA(Asl, 4);
        prefA(Asl, 5);
        prefA(Asl, 6);
        for (int cc = 4; cc < NCH; cc++) {
            if (cc + 3 < NCH) prefA(Asl, cc + 3);
            if      (cc <  NCH - 3) CP_WAIT(3);
            else if (cc == NCH - 3) CP_WAIT(2);
            else if (cc == NCH - 2) CP_WAIT(1);
            else                    CP_WAIT(0);
            BAR_QUAD();
            do_chunk(cc, acc);
        }
        __syncthreads();   // all quads done -> stage region reusable as sg

        // ---- epilogue: acc -> sg[col][m] ----
        #pragma unroll
        for (int mt = 0; mt < 2; mt++) {
            int m0 = wm * 32 + mt * 16 + (lane >> 2);
            #pragma unroll
            for (int nt = 0; nt < 2; nt++) {
                int c0 = wn * 16 + nt * 8 + 2 * (lane & 3);
                sg[c0 * 132 + m0]           = acc[mt][nt][0];
                sg[(c0 + 1) * 132 + m0]     = acc[mt][nt][1];
                sg[c0 * 132 + m0 + 8]       = acc[mt][nt][2];
                sg[(c0 + 1) * 132 + m0 + 8] = acc[mt][nt][3];
            }
        }
        __syncthreads();

        // ---- cell update (c in registers; thread = batch row x 4 j's) ----
        {
            const int b  = tid & 127;
            const int js = (tid >> 7) * 4;       // 0,4,8,12
            const float* bs = sbias[t > 0 ? 1 : 0];
            __align__(8) __half hbuf[4];
            #pragma unroll
            for (int q = 0; q < 4; q++) {
                int jl = js + q;
                float iv = fast_sig (sg[jl * 132 + b]        + bs[jl]);
                float fv = fast_sig (sg[(16 + jl) * 132 + b] + bs[16 + jl]);
                float gv = fast_tanh(sg[(32 + jl) * 132 + b] + bs[32 + jl]);
                float ov = fast_sig (sg[(48 + jl) * 132 + b] + bs[48 + jl]);
                float cnew = fmaf(fv, c_reg[q], iv * gv);
                c_reg[q] = cnew;
                hbuf[q] = __float2half(ov * fast_tanh(cnew));
            }
            __half* hd = g_Ah + (size_t)(t + 1) * BB * K2
                       + (size_t)(mh * 128 + b) * K2 + 256 + j0 + js;
            *(uint2*)hd = *(uint2*)hbuf;
        }
        __syncthreads();   // sg reads done before stages reused

        // ---- tree-barrier arrive + prime next-step mlp chunks ----
        if (t + 1 < SS) {
            if (tid == 0) {
                __threadfence();
                unsigned lo = atomicAdd(&g_leafp[grp * 32], 1u);
                if (((lo + 1) & 7u) == 0u) {
                    unsigned ro = atomicAdd(&g_root, 1u);
                    if (((ro + 1) & 15u) == 0u) {
                        unsigned rv = (ro + 1) >> 4;     // = t+1
                        __threadfence();
                        #pragma unroll
                        for (int i = 0; i < 16; i++)
                            *((volatile unsigned*)&g_relp[i * 32]) = rv;
                    }
                }
            }
            const __half* AslN = Asl + (size_t)BB * K2;
            prefA(AslN, 0);
            prefA(AslN, 1);
            prefA(AslN, 2);
        }
    }
    #undef BAR_QUAD
}

// ---------------- kernel 5: out[b][t][a] = h_t @ Wout^T + bout (fp16 mma) ----------------
__global__ void __launch_bounds__(256, 1)
finalout_kernel(const float* __restrict__ bout, float* __restrict__ dout)
{
    extern __shared__ __half fsm[];
    const int tid  = threadIdx.x;
    const int lane = tid & 31;
    const int w    = tid >> 5;               // warp -> rows [w*16, w*16+16)
    const int tt   = blockIdx.x >> 1;
    const int b0   = (blockIdx.x & 1) * 128;

    const uint32_t sbase = smem_u32(fsm);
    const uint32_t wbase = sbase;                       // Wout image: 16 chunks x 8192 B
    const uint32_t hbase = sbase + FW_HALFS * 2;        // 2 H stages x 16384 B

    const __half* hsl = g_Ah + (size_t)(tt + 1) * BB * K2 + (size_t)b0 * K2 + 256;

    for (int u = tid; u < FW_HALFS / 8; u += 256)
        cpasync16(wbase + u * 16, g_Wfin + (size_t)u * 8);

    auto prefH = [&](int cc) {
        uint32_t sd = hbase + (cc & 1) * FSTG_B;
        #pragma unroll
        for (int i = 0; i < 4; i++) {
            int idx = i * 256 + tid;         // 0..1023 units (128 rows x 8)
            int r = idx >> 3, u = idx & 7;
            cpasync16(sd + r * 128 + ((u ^ (r & 7)) << 4),
                      hsl + (size_t)r * K2 + cc * 64 + u * 8);
        }
        CP_COMMIT();
    };
    prefH(0);

    float acc[8][4];
    #pragma unroll
    for (int nt = 0; nt < 8; nt++)
        #pragma unroll
        for (int r = 0; r < 4; r++) acc[nt][r] = 0.f;

    for (int cc = 0; cc < 16; cc++) {
        if (cc + 1 < 16) { prefH(cc + 1); CP_WAIT(1); }
        else             { CP_WAIT(0); }
        __syncthreads();
        uint32_t sA = hbase + (cc & 1) * FSTG_B;
        uint32_t sB = wbase + cc * 8192;
        #pragma unroll
        for (int ks = 0; ks < 4; ks++) {
            const int ku0 = ks * 2;
            uint32_t af[4], bf[4][4];
            {
                int lr = w * 16 + (lane & 15);
                int ku = (lane >> 4) + ku0;
                ldsm4(af, sA + lr * 128 + ((ku ^ (lr & 7)) << 4));
            }
            #pragma unroll
            for (int nh = 0; nh < 4; nh++) {
                int n  = nh * 16 + (lane & 7) + ((lane >> 4) << 3);
                int ku = ((lane & 8) >> 3) + ku0;
                ldsm4(bf[nh], sB + n * 128 + ((ku ^ (n & 7)) << 4));
            }
            #pragma unroll
            for (int nt = 0; nt < 8; nt++)
                mma_f16(acc[nt], af[0], af[1], af[2], af[3],
                        bf[nt >> 1][(nt & 1) * 2], bf[nt >> 1][(nt & 1) * 2 + 1]);
        }
        __syncthreads();
    }

    const int m0 = w * 16 + (lane >> 2);
    #pragma unroll
    for (int nt = 0; nt < 8; nt++) {
        int a0 = nt * 8 + 2 * (lane & 3);
        float bv0 = __ldg(bout + a0), bv1 = __ldg(bout + a0 + 1);
        float* d0 = dout + (size_t)(b0 + m0) * SS * AA + tt * AA + a0;
        float* d1 = dout + (size_t)(b0 + m0 + 8) * SS * AA + tt * AA + a0;
        d0[0] = acc[nt][0] + bv0;
        d0[1] = acc[nt][1] + bv1;
        d1[0] = acc[nt][2] + bv0;
        d1[1] = acc[nt][3] + bv1;
    }
}

// ---------------- launch ----------------
extern "C" void kernel_launch(void* const* d_in, const int* in_sizes, int n_in,
                              void* d_out, int out_size)
{
    const float* observe  = (const float*)d_in[0];
    const float* obstacle = (const float*)d_in[1];
    const float* mask     = (const float*)d_in[2];
    const float* W1       = (const float*)d_in[3];
    const float* b1       = (const float*)d_in[4];
    const float* W2       = (const float*)d_in[5];
    const float* b2       = (const float*)d_in[6];
    const float* W_ih     = (const float*)d_in[7];
    const float* b_ih     = (const float*)d_in[8];
    const float* W_hh     = (const float*)d_in[9];
    const float* b_hh     = (const float*)d_in[10];
    const float* W_out    = (const float*)d_in[11];
    const float* b_out    = (const float*)d_in[12];
    float* out = (float*)d_out;

    cudaFuncSetAttribute(lstm_kernel, cudaFuncAttributeMaxDynamicSharedMemorySize, SMEM_BYTES);
    cudaFuncSetAttribute(finalout_kernel, cudaFuncAttributeMaxDynamicSharedMemorySize, FOUT_SMEM);

    bias_kernel<<<16, 256>>>(W2, b1, b2, b_ih, b_hh, W_ih, b_out);
    collapse_kernel<<<IN_D, 256>>>(W1, W2);
    wprep_kernel<<<64, 256>>>(W_ih, W_hh, W_out);
    wfin_kernel<<<16, 256>>>(W_out);
    mlp_kernel<<<SS * 16, 256>>>(observe, obstacle, mask);
    lstm_kernel<<<NCTA, NTHR, SMEM_BYTES>>>(0);
    finalout_kernel<<<SS * 2, 256, FOUT_SMEM>>>(b_out, out);
}

// round 16
// speedup vs baseline: 2.0497x; 1.0333x over previous
#include <cuda_runtime.h>
#include <cuda_fp16.h>
#include <math.h>
#include <stdint.h>

// Problem constants
#define BB    256
#define SS    128
#define IN_D  192
#define MLP_O 256
#define HH    1024
#define AA    64
#define K2    1280          // MLP_O + HH (o_prev folded away)
#define CK    64            // K per chunk
#define NCH   20            // K2/CK  (chunks 0..3 = mlp part, 4..19 = h part)
#define G4    4096
#define NCTA  128
#define NTHR  512           // lstm threads (16 warps)

// lstm smem geometry (halfs) — W persistent + per-quad swizzled A stages
#define W_HALFS  (NCH * 64 * CK)       // 81920 halfs = 160 KB
#define ASTG2_B  4096                  // bytes per quad stage (32 rows x 64 halfs)
#define NSTG     4
#define A_HALFS  (4 * NSTG * (ASTG2_B / 2))              // 32768 halfs = 64 KB
#define SMEM_BYTES ((W_HALFS + A_HALFS) * 2)             // 229376 B

// finalout smem: Wout image (16 chunks x 4096 halfs = 128 KB) + 2 H stages (16 KB each)
#define FW_HALFS  (16 * 64 * 64)                          // 65536 halfs = 128 KB
#define FSTG_B    16384                                   // 128 rows x 128 B
#define FOUT_SMEM (FW_HALFS * 2 + 2 * FSTG_B)             // 163840 B

// mlp mma smem: Wc image (3 chunks x 256 cols x 64 k = 96 KB) + X tile (3 x 16 KB)
#define MW_BYTES  (3 * MLP_O * CK * 2)                    // 98304
#define MX_BYTES  (3 * 128 * 128)                         // 49152
#define MLP_SMEM  (MW_BYTES + MX_BYTES)                   // 147456

// ---------------- device scratch ----------------
__device__ float g_bc[MLP_O];
__device__ float g_bias0[G4];        // b_ih + b_hh             (t == 0)
__device__ float g_bias1[G4];        // + W_ihA @ bout          (t >= 1)
__device__ __align__(16) __half g_Wmlp[3 * MLP_O * CK];           // collapsed Wc fp16 image
__device__ __align__(16) __half g_Wph[64 * W_HALFS];              // packed swizzled fp16 W
__device__ __align__(16) __half g_Wfin[FW_HALFS];                 // packed swizzled fp16 Wout
__device__ __align__(16) __half g_Ah[(size_t)(SS + 1) * BB * K2]; // [t][b][k] slabs fp16
__device__ unsigned g_cnt = 0;
__device__ unsigned g_gen = 0;
// tree barrier state (padded: one 128B line per counter)
__device__ unsigned g_leafp[16 * 32];
__device__ unsigned g_relp[16 * 32];
__device__ unsigned g_root = 0;

__device__ __forceinline__ uint32_t smem_u32(const void* p)
{
    uint32_t a;
    asm("{ .reg .u64 t; cvta.to.shared.u64 t, %1; cvt.u32.u64 %0, t; }" : "=r"(a) : "l"(p));
    return a;
}

__device__ __forceinline__ void cpasync16(uint32_t dst, const void* src)
{
    asm volatile("cp.async.cg.shared.global [%0], [%1], 16;" :: "r"(dst), "l"(src));
}
#define CP_COMMIT() asm volatile("cp.async.commit_group;")
#define CP_WAIT(N)  asm volatile("cp.async.wait_group %0;" :: "n"(N))

__device__ __forceinline__ void ldsm4(uint32_t r[4], uint32_t addr)
{
    asm volatile("ldmatrix.sync.aligned.m8n8.x4.shared.b16 {%0,%1,%2,%3}, [%4];"
                 : "=r"(r[0]), "=r"(r[1]), "=r"(r[2]), "=r"(r[3]) : "r"(addr));
}

__device__ __forceinline__ void mma_f16(float c[4],
                                        uint32_t a0, uint32_t a1, uint32_t a2, uint32_t a3,
                                        uint32_t b0, uint32_t b1)
{
    asm("mma.sync.aligned.m16n8k16.row.col.f32.f16.f16.f32 "
        "{%0,%1,%2,%3}, {%4,%5,%6,%7}, {%8,%9}, {%0,%1,%2,%3};"
        : "+f"(c[0]), "+f"(c[1]), "+f"(c[2]), "+f"(c[3])
        : "r"(a0), "r"(a1), "r"(a2), "r"(a3), "r"(b0), "r"(b1));
}

__device__ __forceinline__ float fast_sig(float x)
{
    return 1.f / (1.f + __expf(-x));
}
__device__ __forceinline__ float fast_tanh(float x)
{
    x = fminf(fmaxf(x, -15.f), 15.f);
    float e = __expf(2.f * x);
    return (e - 1.f) / (e + 1.f);
}

// ---------------- full grid barrier (init only) ----------------
__device__ __forceinline__ void grid_barrier(unsigned &gen)
{
    __syncthreads();
    if (threadIdx.x == 0) {
        __threadfence();
        unsigned ticket = atomicAdd(&g_cnt, 1u);
        if (ticket == NCTA - 1u) {
            g_cnt = 0u;
            __threadfence();
            atomicAdd(&g_gen, 1u);
        } else {
            while (*((volatile unsigned *)&g_gen) == gen) { }
            __threadfence();
        }
    }
    gen += 1u;
    __syncthreads();
}

// ---------------- kernel 0: biases ----------------
__global__ void bias_kernel(const float* __restrict__ W2, const float* __restrict__ b1,
                            const float* __restrict__ b2, const float* __restrict__ bih,
                            const float* __restrict__ bhh, const float* __restrict__ Wih,
                            const float* __restrict__ bout)
{
    int n = blockIdx.x * 256 + threadIdx.x;
    float base = bih[n] + bhh[n];
    float fold = 0.f;
    const float* wa = Wih + n * 320 + 256;
    #pragma unroll
    for (int a = 0; a < 64; a++) fold = fmaf(wa[a], bout[a], fold);
    g_bias0[n] = base;
    g_bias1[n] = base + fold;

    if (blockIdx.x == 0) {
        int tid = threadIdx.x;
        const float* w2r = W2 + tid * 1024;
        float acc = b2[tid];
        #pragma unroll 4
        for (int h = 0; h < 1024; h += 4) {
            float4 w = *(const float4*)(w2r + h);
            acc = fmaf(w.x, b1[h], acc);
            acc = fmaf(w.y, b1[h+1], acc);
            acc = fmaf(w.z, b1[h+2], acc);
            acc = fmaf(w.w, b1[h+3], acc);
        }
        g_bc[tid] = acc;
    }
}

// ---------------- kernel 1: collapse W2@W1 -> fp16 SW128 image g_Wmlp ----------------
__global__ void collapse_kernel(const float* __restrict__ W1, const float* __restrict__ W2)
{
    __shared__ float w1k[1024];
    int k = blockIdx.x;              // 0..191
    for (int h = threadIdx.x; h < 1024; h += 256) w1k[h] = W1[h * IN_D + k];
    __syncthreads();
    int o = threadIdx.x;             // 0..255 (output col = mma B row)
    const float* w2r = W2 + o * 1024;
    float acc = 0.f;
    #pragma unroll 4
    for (int h = 0; h < 1024; h += 4) {
        float4 w = *(const float4*)(w2r + h);
        acc = fmaf(w.x, w1k[h],   acc);
        acc = fmaf(w.y, w1k[h+1], acc);
        acc = fmaf(w.z, w1k[h+2], acc);
        acc = fmaf(w.w, w1k[h+3], acc);
    }
    int ch = k >> 6, kk = k & 63;
    int sw = ((kk >> 3) & 7) ^ (o & 7);
    g_Wmlp[ch * (MLP_O * CK) + o * 64 + sw * 8 + (kk & 7)] = __float2half(acc);
}

// ---------------- kernel 2: pack fused+folded weights (fp16, swizzled smem image) ----------------
__global__ void wprep_kernel(const float* __restrict__ Wih, const float* __restrict__ Whh,
                             const float* __restrict__ Wout)
{
    __shared__ float As[64 * 68];
    __shared__ float Wc[64 * 68];
    const int jb  = blockIdx.x;
    const int tid = threadIdx.x;
    __half* wp = g_Wph + (size_t)jb * W_HALFS;

    #pragma unroll
    for (int q = 0; q < 16; q++) {
        int idx = q * 256 + tid;
        int col = idx >> 6, a = idx & 63;
        int row = (col >> 4) * 1024 + jb * 16 + (col & 15);
        As[col * 68 + a] = Wih[row * 320 + 256 + a];
    }
    #pragma unroll 4
    for (int q = 0; q < 64; q++) {
        int idx = q * 256 + tid;
        int col = idx >> 8, k = idx & 255;
        int row = (col >> 4) * 1024 + jb * 16 + (col & 15);
        int sw  = ((k >> 3) & 7) ^ (col & 7);
        wp[(k >> 6) * 4096 + col * 64 + sw * 8 + (k & 7)] = __float2half(Wih[row * 320 + k]);
    }
    __syncthreads();

    const int col = tid & 63;
    const int hq  = tid >> 6;
    const int row = (col >> 4) * 1024 + jb * 16 + (col & 15);
    for (int hc = 0; hc < 16; hc++) {
        #pragma unroll 4
        for (int q = 0; q < 16; q++) {
            int idx = q * 256 + tid;
            int a = idx >> 6, h = idx & 63;
            Wc[a * 68 + h] = Wout[a * 1024 + hc * 64 + h];
        }
        __syncthreads();
        #pragma unroll 2
        for (int i = 0; i < 16; i++) {
            int h  = hq * 16 + i;
            int hh = hc * 64 + h;
            float fold = 0.f;
            #pragma unroll 8
            for (int a = 0; a < 64; a++)
                fold = fmaf(As[col * 68 + a], Wc[a * 68 + h], fold);
            float val = Whh[row * 1024 + hh] + fold;
            int k = 256 + hh;
            int sw = ((k >> 3) & 7) ^ (col & 7);
            wp[(k >> 6) * 4096 + col * 64 + sw * 8 + (k & 7)] = __float2half(val);
        }
        __syncthreads();
    }
}

// ---------------- kernel 2b: pack Wout fp16 swizzled image for finalout ----------------
__global__ void wfin_kernel(const float* __restrict__ Wout)
{
    const int cc  = blockIdx.x;
    const int tid = threadIdx.x;
    __half* wp = g_Wfin + cc * 4096;
    #pragma unroll
    for (int q = 0; q < 16; q++) {
        int idx = q * 256 + tid;
        int n = idx >> 6, kk = idx & 63;
        int sw = ((kk >> 3) & 7) ^ (n & 7);
        wp[n * 64 + sw * 8 + (kk & 7)] = __float2half(Wout[n * 1024 + cc * 64 + kk]);
    }
}

// ---------------- kernel 3: mlp via fp16 mma -> g_Ah[s][b][k] ----------------
__global__ void __launch_bounds__(512, 1)
mlp_kernel(const float* __restrict__ observe,
           const float* __restrict__ obstacle,
           const float* __restrict__ mask)
{
    extern __shared__ __half msm[];
    __shared__ float sbc[MLP_O];
    const int tid  = threadIdx.x;
    const int lane = tid & 31;
    const int w    = tid >> 5;               // 0..15
    const int s    = blockIdx.x >> 1;
    const int b0   = (blockIdx.x & 1) * 128;

    const uint32_t sbase = smem_u32(msm);
    const uint32_t wbase = sbase;            // Wc image: 3 chunks x 32768 B
    const uint32_t xbase = sbase + MW_BYTES; // X tile:  3 chunks x 16384 B

    // load Wc image (96 KB) via cp.async
    for (int u = tid; u < MW_BYTES / 16; u += 512)
        cpasync16(wbase + u * 16, g_Wmlp + (size_t)u * 8);
    CP_COMMIT();
    for (int i = tid; i < MLP_O; i += 512) sbc[i] = g_bc[i];

    // build X tile: 128 tokens (b0..b0+127) x 192 features, swizzled fp16
    for (int idx = tid; idx < 128 * IN_D; idx += 512) {
        int r = idx / IN_D, k = idx - r * IN_D;
        int p = (b0 + r) * 128 + s;
        float v;
        if (k < 64) v = observe[p * 64 + k];
        else {
            int kk2 = k - 64;
            v = obstacle[p * 128 + kk2] * mask[p * 8 + (kk2 >> 4)];
        }
        int ch = k >> 6, kk = k & 63;
        uint32_t addr = xbase + ch * 16384 + r * 128
                      + ((((kk >> 3) & 7) ^ (r & 7)) << 4) + (kk & 7) * 2;
        *(__half*)(msm + (addr - sbase) / 2) = __float2half(v);
    }
    CP_WAIT(0);
    __syncthreads();

    // mma: warp w -> rows [(w&7)*16, +16), col half (w>>3)*128
    const int m0 = (w & 7) * 16;
    const int nb = (w >> 3) * 128;
    float acc[16][4];
    #pragma unroll
    for (int nt = 0; nt < 16; nt++)
        #pragma unroll
        for (int r = 0; r < 4; r++) acc[nt][r] = 0.f;

    for (int ch = 0; ch < 3; ch++) {
        uint32_t sA = xbase + ch * 16384;
        uint32_t sB = wbase + ch * 32768;
        #pragma unroll
        for (int ks = 0; ks < 4; ks++) {
            const int ku0 = ks * 2;
            uint32_t af[4], bf[8][4];
            {
                int lr = m0 + (lane & 15);
                int ku = (lane >> 4) + ku0;
                ldsm4(af, sA + lr * 128 + ((ku ^ (lr & 7)) << 4));
            }
            #pragma unroll
            for (int nh = 0; nh < 8; nh++) {
                int n  = nb + nh * 16 + (lane & 7) + ((lane >> 4) << 3);
                int ku = ((lane & 8) >> 3) + ku0;
                ldsm4(bf[nh], sB + n * 128 + ((ku ^ (n & 7)) << 4));
            }
            #pragma unroll
            for (int nt = 0; nt < 16; nt++)
                mma_f16(acc[nt], af[0], af[1], af[2], af[3],
                        bf[nt >> 1][(nt & 1) * 2], bf[nt >> 1][(nt & 1) * 2 + 1]);
        }
    }

    // epilogue: bias + relu -> fp16 pairs -> g_Ah[s][b][col]
    const int r0 = m0 + (lane >> 2);
    __half* dst = g_Ah + (size_t)s * BB * K2 + (size_t)b0 * K2;
    #pragma unroll
    for (int nt = 0; nt < 16; nt++) {
        int a0 = nb + nt * 8 + 2 * (lane & 3);
        float bv0 = sbc[a0], bv1 = sbc[a0 + 1];
        __half2 v0 = __floats2half2_rn(fmaxf(acc[nt][0] + bv0, 0.f),
                                       fmaxf(acc[nt][1] + bv1, 0.f));
        __half2 v1 = __floats2half2_rn(fmaxf(acc[nt][2] + bv0, 0.f),
                                       fmaxf(acc[nt][3] + bv1, 0.f));
        *(__half2*)(dst + (size_t)r0 * K2 + a0)       = v0;
        *(__half2*)(dst + (size_t)(r0 + 8) * K2 + a0) = v1;
    }
}

// ---------------- kernel 4: persistent LSTM (16 warps, tree barrier) ----------------
__global__ void __launch_bounds__(NTHR, 1)
lstm_kernel(int dummy)
{
    extern __shared__ __half smh[];
    float* sg = (float*)(smh + W_HALFS);
    __shared__ float sbias[2][64];

    const int tid  = threadIdx.x;
    const int cta  = blockIdx.x;
    const int mh   = cta & 1;
    const int jb   = cta >> 1;
    const int j0   = jb * 16;
    const int lane = tid & 31;
    const int w    = tid >> 5;
    const int wm   = w & 3;
    const int wn   = w >> 2;
    const int grp  = cta >> 3;
    unsigned gen = *((volatile unsigned*)&g_gen);

    const uint32_t sbase = smem_u32(smh);
    const uint32_t wbase = sbase;
    const uint32_t abase = sbase + W_HALFS * 2;

    {
        const __half* src = g_Wph + (size_t)jb * W_HALFS;
        for (int u = tid; u < W_HALFS / 8; u += NTHR)
            cpasync16(wbase + u * 16, src + (size_t)u * 8);
        CP_COMMIT();
    }

    const int gt = cta * NTHR + tid;
    for (int i = gt; i < (HH * BB) / 2; i += NCTA * NTHR) {
        int b = i >> 9, off = (i & 511) * 2;
        *(uint32_t*)&g_Ah[(size_t)b * K2 + 256 + off] = 0u;
    }
    if (gt < 16 * 32) { g_leafp[gt] = 0u; g_relp[gt] = 0u; }
    if (gt == 16 * 32) g_root = 0u;
    if (tid < 64) {
        int gate = tid >> 4, jl = tid & 15;
        sbias[0][tid] = g_bias0[gate * 1024 + j0 + jl];
        sbias[1][tid] = g_bias1[gate * 1024 + j0 + jl];
    }
    float c_reg[4];
    #pragma unroll
    for (int q = 0; q < 4; q++) c_reg[q] = 0.f;
    CP_WAIT(0);
    grid_barrier(gen);

    #define BAR_QUAD() asm volatile("bar.sync %0, %1;" :: "r"(wm + 1), "r"(128) : "memory")

    auto prefA = [&](const __half* Asl, int cc) {
        uint32_t sd = abase + (wm * NSTG + (cc & 3)) * ASTG2_B;
        const __half* src = Asl + (size_t)(wm * 32) * K2 + cc * CK;
        #pragma unroll
        for (int i = 0; i < 2; i++) {
            int idx = i * 128 + wn * 32 + lane;
            int r = idx >> 3, u = idx & 7;
            cpasync16(sd + r * 128 + ((u ^ (r & 7)) << 4), src + (size_t)r * K2 + u * 8);
        }
        CP_COMMIT();
    };

    auto do_chunk = [&](int cc, float (&acc)[2][2][4]) {
        uint32_t sA = abase + (wm * NSTG + (cc & 3)) * ASTG2_B;
        uint32_t sB = wbase + cc * 8192;
        #pragma unroll
        for (int ks = 0; ks < 4; ks++) {
            const int ku0 = ks * 2;
            uint32_t af[2][4], bf[4];
            #pragma unroll
            for (int mt = 0; mt < 2; mt++) {
                int lr = mt * 16 + (lane & 15);
                int ku = (lane >> 4) + ku0;
                ldsm4(af[mt], sA + lr * 128 + ((ku ^ (lr & 7)) << 4));
            }
            {
                int n  = wn * 16 + (lane & 7) + ((lane >> 4) << 3);
                int ku = ((lane & 8) >> 3) + ku0;
                ldsm4(bf, sB + n * 128 + ((ku ^ (n & 7)) << 4));
            }
            #pragma unroll
            for (int mt = 0; mt < 2; mt++)
                #pragma unroll
                for (int nt = 0; nt < 2; nt++)
                    mma_f16(acc[mt][nt],
                            af[mt][0], af[mt][1], af[mt][2], af[mt][3],
                            bf[nt * 2], bf[nt * 2 + 1]);
        }
    };

    prefA(g_Ah + (size_t)mh * 128 * K2, 0);
    prefA(g_Ah + (size_t)mh * 128 * K2, 1);
    prefA(g_Ah + (size_t)mh * 128 * K2, 2);

    for (int t = 0; t < SS; ++t) {
        const __half* Asl = g_Ah + (size_t)t * BB * K2 + (size_t)mh * 128 * K2;

        float acc[2][2][4];
        #pragma unroll
        for (int mt = 0; mt < 2; mt++)
            #pragma unroll
            for (int nt = 0; nt < 2; nt++)
                #pragma unroll
                for (int r = 0; r < 4; r++) acc[mt][nt][r] = 0.f;

        for (int cc = 0; cc < 4; cc++) {
            if (cc == 0) prefA(Asl, 3);
            if      (cc == 0) CP_WAIT(3);
            else if (cc == 1) CP_WAIT(2);
            else if (cc == 2) CP_WAIT(1);
            else              CP_WAIT(0);
            BAR_QUAD();
            do_chunk(cc, acc);
        }

        if (t > 0) {
            if (tid == 0) {
                const volatile unsigned* rl = &g_relp[grp * 32];
                while (*rl < (unsigned)t) { }
                __threadfence();
            }
        }
        __syncthreads();

        prefA(Asl, 4);
        prefA(Asl, 5);
        prefA(Asl, 6);
        for (int cc = 4; cc < NCH; cc++) {
            if (cc + 3 < NCH) prefA(Asl, cc + 3);
            if      (cc <  NCH - 3) CP_WAIT(3);
            else if (cc == NCH - 3) CP_WAIT(2);
            else if (cc == NCH - 2) CP_WAIT(1);
            else                    CP_WAIT(0);
            BAR_QUAD();
            do_chunk(cc, acc);
        }
        __syncthreads();

        #pragma unroll
        for (int mt = 0; mt < 2; mt++) {
            int m0 = wm * 32 + mt * 16 + (lane >> 2);
            #pragma unroll
            for (int nt = 0; nt < 2; nt++) {
                int c0 = wn * 16 + nt * 8 + 2 * (lane & 3);
                sg[c0 * 132 + m0]           = acc[mt][nt][0];
                sg[(c0 + 1) * 132 + m0]     = acc[mt][nt][1];
                sg[c0 * 132 + m0 + 8]       = acc[mt][nt][2];
                sg[(c0 + 1) * 132 + m0 + 8] = acc[mt][nt][3];
            }
        }
        __syncthreads();

        {
            const int b  = tid & 127;
            const int js = (tid >> 7) * 4;
            const float* bs = sbias[t > 0 ? 1 : 0];
            __align__(8) __half hbuf[4];
            #pragma unroll
            for (int q = 0; q < 4; q++) {
                int jl = js + q;
                float iv = fast_sig (sg[jl * 132 + b]        + bs[jl]);
                float fv = fast_sig (sg[(16 + jl) * 132 + b] + bs[16 + jl]);
                float gv = fast_tanh(sg[(32 + jl) * 132 + b] + bs[32 + jl]);
                float ov = fast_sig (sg[(48 + jl) * 132 + b] + bs[48 + jl]);
                float cnew = fmaf(fv, c_reg[q], iv * gv);
                c_reg[q] = cnew;
                hbuf[q] = __float2half(ov * fast_tanh(cnew));
            }
            __half* hd = g_Ah + (size_t)(t + 1) * BB * K2
                       + (size_t)(mh * 128 + b) * K2 + 256 + j0 + js;
            *(uint2*)hd = *(uint2*)hbuf;
        }
        __syncthreads();

        if (t + 1 < SS) {
            if (tid == 0) {
                __threadfence();
                unsigned lo = atomicAdd(&g_leafp[grp * 32], 1u);
                if (((lo + 1) & 7u) == 0u) {
                    unsigned ro = atomicAdd(&g_root, 1u);
                    if (((ro + 1) & 15u) == 0u) {
                        unsigned rv = (ro + 1) >> 4;
                        __threadfence();
                        #pragma unroll
                        for (int i = 0; i < 16; i++)
                            *((volatile unsigned*)&g_relp[i * 32]) = rv;
                    }
                }
            }
            const __half* AslN = Asl + (size_t)BB * K2;
            prefA(AslN, 0);
            prefA(AslN, 1);
            prefA(AslN, 2);
        }
    }
    #undef BAR_QUAD
}

// ---------------- kernel 5: out[b][t][a] = h_t @ Wout^T + bout (fp16 mma) ----------------
__global__ void __launch_bounds__(256, 1)
finalout_kernel(const float* __restrict__ bout, float* __restrict__ dout)
{
    extern __shared__ __half fsm[];
    const int tid  = threadIdx.x;
    const int lane = tid & 31;
    const int w    = tid >> 5;
    const int tt   = blockIdx.x >> 1;
    const int b0   = (blockIdx.x & 1) * 128;

    const uint32_t sbase = smem_u32(fsm);
    const uint32_t wbase = sbase;
    const uint32_t hbase = sbase + FW_HALFS * 2;

    const __half* hsl = g_Ah + (size_t)(tt + 1) * BB * K2 + (size_t)b0 * K2 + 256;

    for (int u = tid; u < FW_HALFS / 8; u += 256)
        cpasync16(wbase + u * 16, g_Wfin + (size_t)u * 8);

    auto prefH = [&](int cc) {
        uint32_t sd = hbase + (cc & 1) * FSTG_B;
        #pragma unroll
        for (int i = 0; i < 4; i++) {
            int idx = i * 256 + tid;
            int r = idx >> 3, u = idx & 7;
            cpasync16(sd + r * 128 + ((u ^ (r & 7)) << 4),
                      hsl + (size_t)r * K2 + cc * 64 + u * 8);
        }
        CP_COMMIT();
    };
    prefH(0);

    float acc[8][4];
    #pragma unroll
    for (int nt = 0; nt < 8; nt++)
        #pragma unroll
        for (int r = 0; r < 4; r++) acc[nt][r] = 0.f;

    for (int cc = 0; cc < 16; cc++) {
        if (cc + 1 < 16) { prefH(cc + 1); CP_WAIT(1); }
        else             { CP_WAIT(0); }
        __syncthreads();
        uint32_t sA = hbase + (cc & 1) * FSTG_B;
        uint32_t sB = wbase + cc * 8192;
        #pragma unroll
        for (int ks = 0; ks < 4; ks++) {
            const int ku0 = ks * 2;
            uint32_t af[4], bf[4][4];
            {
                int lr = w * 16 + (lane & 15);
                int ku = (lane >> 4) + ku0;
                ldsm4(af, sA + lr * 128 + ((ku ^ (lr & 7)) << 4));
            }
            #pragma unroll
            for (int nh = 0; nh < 4; nh++) {
                int n  = nh * 16 + (lane & 7) + ((lane >> 4) << 3);
                int ku = ((lane & 8) >> 3) + ku0;
                ldsm4(bf[nh], sB + n * 128 + ((ku ^ (n & 7)) << 4));
            }
            #pragma unroll
            for (int nt = 0; nt < 8; nt++)
                mma_f16(acc[nt], af[0], af[1], af[2], af[3],
                        bf[nt >> 1][(nt & 1) * 2], bf[nt >> 1][(nt & 1) * 2 + 1]);
        }
        __syncthreads();
    }

    const int m0 = w * 16 + (lane >> 2);
    #pragma unroll
    for (int nt = 0; nt < 8; nt++) {
        int a0 = nt * 8 + 2 * (lane & 3);
        float bv0 = __ldg(bout + a0), bv1 = __ldg(bout + a0 + 1);
        float* d0 = dout + (size_t)(b0 + m0) * SS * AA + tt * AA + a0;
        float* d1 = dout + (size_t)(b0 + m0 + 8) * SS * AA + tt * AA + a0;
        d0[0] = acc[nt][0] + bv0;
        d0[1] = acc[nt][1] + bv1;
        d1[0] = acc[nt][2] + bv0;
        d1[1] = acc[nt][3] + bv1;
    }
}

// ---------------- launch ----------------
extern "C" void kernel_launch(void* const* d_in, const int* in_sizes, int n_in,
                              void* d_out, int out_size)
{
    const float* observe  = (const float*)d_in[0];
    const float* obstacle = (const float*)d_in[1];
    const float* mask     = (const float*)d_in[2];
    const float* W1       = (const float*)d_in[3];
    const float* b1       = (const float*)d_in[4];
    const float* W2       = (const float*)d_in[5];
    const float* b2       = (const float*)d_in[6];
    const float* W_ih     = (const float*)d_in[7];
    const float* b_ih     = (const float*)d_in[8];
    const float* W_hh     = (const float*)d_in[9];
    const float* b_hh     = (const float*)d_in[10];
    const float* W_out    = (const float*)d_in[11];
    const float* b_out    = (const float*)d_in[12];
    float* out = (float*)d_out;

    cudaFuncSetAttribute(lstm_kernel, cudaFuncAttributeMaxDynamicSharedMemorySize, SMEM_BYTES);
    cudaFuncSetAttribute(finalout_kernel, cudaFuncAttributeMaxDynamicSharedMemorySize, FOUT_SMEM);
    cudaFuncSetAttribute(mlp_kernel, cudaFuncAttributeMaxDynamicSharedMemorySize, MLP_SMEM);

    bias_kernel<<<16, 256>>>(W2, b1, b2, b_ih, b_hh, W_ih, b_out);
    collapse_kernel<<<IN_D, 256>>>(W1, W2);
    wprep_kernel<<<64, 256>>>(W_ih, W_hh, W_out);
    wfin_kernel<<<16, 256>>>(W_out);
    mlp_kernel<<<SS * 2, 512, MLP_SMEM>>>(observe, obstacle, mask);
    lstm_kernel<<<NCTA, NTHR, SMEM_BYTES>>>(0);
    finalout_kernel<<<SS * 2, 256, FOUT_SMEM>>>(b_out, out);
}

// round 17
// speedup vs baseline: 2.0601x; 1.0051x over previous
#include <cuda_runtime.h>
#include <cuda_fp16.h>
#include <math.h>
#include <stdint.h>

// Problem constants
#define BB    256
#define SS    128
#define IN_D  192
#define MLP_O 256
#define HH    1024
#define AA    64
#define K2    1280          // MLP_O + HH (o_prev folded away)
#define CK    64            // K per chunk
#define NCH   20            // K2/CK  (chunks 0..3 = mlp part, 4..19 = h part)
#define G4    4096
#define NCTA  128
#define NTHR  512           // lstm threads (16 warps)

// lstm smem geometry (halfs) — W persistent + per-quad swizzled A stages
#define W_HALFS  (NCH * 64 * CK)       // 81920 halfs = 160 KB
#define ASTG2_B  4096                  // bytes per quad stage (32 rows x 64 halfs)
#define NSTG     4
#define A_HALFS  (4 * NSTG * (ASTG2_B / 2))              // 32768 halfs = 64 KB
#define SMEM_BYTES ((W_HALFS + A_HALFS) * 2)             // 229376 B

// finalout smem: Wout image (16 chunks x 4096 halfs = 128 KB) + 2 H stages (16 KB each)
#define FW_HALFS  (16 * 64 * 64)                          // 65536 halfs = 128 KB
#define FSTG_B    16384                                   // 128 rows x 128 B
#define FOUT_SMEM (FW_HALFS * 2 + 2 * FSTG_B)             // 163840 B

// mlp mma smem: Wc image (3 chunks x 256 cols x 64 k = 96 KB) + X tile (3 x 16 KB)
#define MW_BYTES  (3 * MLP_O * CK * 2)                    // 98304
#define MX_BYTES  (3 * 128 * 128)                         // 49152
#define MLP_SMEM  (MW_BYTES + MX_BYTES)                   // 147456

// ---------------- device scratch ----------------
__device__ float g_bc[MLP_O];
__device__ float g_bias0[G4];        // b_ih + b_hh             (t == 0)
__device__ float g_bias1[G4];        // + W_ihA @ bout          (t >= 1)
__device__ __align__(16) __half g_Wmlp[3 * MLP_O * CK];           // collapsed Wc fp16 image
__device__ __align__(16) __half g_Wph[64 * W_HALFS];              // packed swizzled fp16 W
__device__ __align__(16) __half g_Wfin[FW_HALFS];                 // packed swizzled fp16 Wout
__device__ __align__(16) __half g_Ah[(size_t)(SS + 1) * BB * K2]; // [t][b][k] slabs fp16
__device__ unsigned g_cnt = 0;
__device__ unsigned g_gen = 0;
// tree barrier state (padded: one 128B line per counter)
__device__ unsigned g_leafp[16 * 32];
__device__ unsigned g_relp[16 * 32];
__device__ unsigned g_root = 0;

__device__ __forceinline__ uint32_t smem_u32(const void* p)
{
    uint32_t a;
    asm("{ .reg .u64 t; cvta.to.shared.u64 t, %1; cvt.u32.u64 %0, t; }" : "=r"(a) : "l"(p));
    return a;
}

__device__ __forceinline__ void cpasync16(uint32_t dst, const void* src)
{
    asm volatile("cp.async.cg.shared.global [%0], [%1], 16;" :: "r"(dst), "l"(src));
}
#define CP_COMMIT() asm volatile("cp.async.commit_group;")
#define CP_WAIT(N)  asm volatile("cp.async.wait_group %0;" :: "n"(N))

__device__ __forceinline__ void ldsm4(uint32_t r[4], uint32_t addr)
{
    asm volatile("ldmatrix.sync.aligned.m8n8.x4.shared.b16 {%0,%1,%2,%3}, [%4];"
                 : "=r"(r[0]), "=r"(r[1]), "=r"(r[2]), "=r"(r[3]) : "r"(addr));
}

__device__ __forceinline__ void mma_f16(float c[4],
                                        uint32_t a0, uint32_t a1, uint32_t a2, uint32_t a3,
                                        uint32_t b0, uint32_t b1)
{
    asm("mma.sync.aligned.m16n8k16.row.col.f32.f16.f16.f32 "
        "{%0,%1,%2,%3}, {%4,%5,%6,%7}, {%8,%9}, {%0,%1,%2,%3};"
        : "+f"(c[0]), "+f"(c[1]), "+f"(c[2]), "+f"(c[3])
        : "r"(a0), "r"(a1), "r"(a2), "r"(a3), "r"(b0), "r"(b1));
}

__device__ __forceinline__ float fast_sig(float x)
{
    return 1.f / (1.f + __expf(-x));
}
__device__ __forceinline__ float fast_tanh(float x)
{
    x = fminf(fmaxf(x, -15.f), 15.f);
    float e = __expf(2.f * x);
    return (e - 1.f) / (e + 1.f);
}

// ---------------- full grid barrier (init only) ----------------
__device__ __forceinline__ void grid_barrier(unsigned &gen)
{
    __syncthreads();
    if (threadIdx.x == 0) {
        __threadfence();
        unsigned ticket = atomicAdd(&g_cnt, 1u);
        if (ticket == NCTA - 1u) {
            g_cnt = 0u;
            __threadfence();
            atomicAdd(&g_gen, 1u);
        } else {
            while (*((volatile unsigned *)&g_gen) == gen) { }
            __threadfence();
        }
    }
    gen += 1u;
    __syncthreads();
}

// ---------------- kernel 0: biases ----------------
__global__ void bias_kernel(const float* __restrict__ W2, const float* __restrict__ b1,
                            const float* __restrict__ b2, const float* __restrict__ bih,
                            const float* __restrict__ bhh, const float* __restrict__ Wih,
                            const float* __restrict__ bout)
{
    int n = blockIdx.x * 256 + threadIdx.x;
    float base = bih[n] + bhh[n];
    float fold = 0.f;
    const float* wa = Wih + n * 320 + 256;
    #pragma unroll
    for (int a = 0; a < 64; a++) fold = fmaf(wa[a], bout[a], fold);
    g_bias0[n] = base;
    g_bias1[n] = base + fold;

    if (blockIdx.x == 0) {
        int tid = threadIdx.x;
        const float* w2r = W2 + tid * 1024;
        float acc = b2[tid];
        #pragma unroll 4
        for (int h = 0; h < 1024; h += 4) {
            float4 w = *(const float4*)(w2r + h);
            acc = fmaf(w.x, b1[h], acc);
            acc = fmaf(w.y, b1[h+1], acc);
            acc = fmaf(w.z, b1[h+2], acc);
            acc = fmaf(w.w, b1[h+3], acc);
        }
        g_bc[tid] = acc;
    }
}

// ---------------- kernel 1: collapse W2@W1 -> fp16 SW128 image g_Wmlp ----------------
__global__ void collapse_kernel(const float* __restrict__ W1, const float* __restrict__ W2)
{
    __shared__ float w1k[1024];
    int k = blockIdx.x;              // 0..191
    for (int h = threadIdx.x; h < 1024; h += 256) w1k[h] = W1[h * IN_D + k];
    __syncthreads();
    int o = threadIdx.x;             // 0..255 (output col = mma B row)
    const float* w2r = W2 + o * 1024;
    float acc = 0.f;
    #pragma unroll 4
    for (int h = 0; h < 1024; h += 4) {
        float4 w = *(const float4*)(w2r + h);
        acc = fmaf(w.x, w1k[h],   acc);
        acc = fmaf(w.y, w1k[h+1], acc);
        acc = fmaf(w.z, w1k[h+2], acc);
        acc = fmaf(w.w, w1k[h+3], acc);
    }
    int ch = k >> 6, kk = k & 63;
    int sw = ((kk >> 3) & 7) ^ (o & 7);
    g_Wmlp[ch * (MLP_O * CK) + o * 64 + sw * 8 + (kk & 7)] = __float2half(acc);
}

// ---------------- kernel 2: pack fused+folded weights (fp16, swizzled smem image) ----------------
__global__ void wprep_kernel(const float* __restrict__ Wih, const float* __restrict__ Whh,
                             const float* __restrict__ Wout)
{
    __shared__ float As[64 * 68];
    __shared__ float Wc[64 * 68];
    const int jb  = blockIdx.x;
    const int tid = threadIdx.x;
    __half* wp = g_Wph + (size_t)jb * W_HALFS;

    #pragma unroll
    for (int q = 0; q < 16; q++) {
        int idx = q * 256 + tid;
        int col = idx >> 6, a = idx & 63;
        int row = (col >> 4) * 1024 + jb * 16 + (col & 15);
        As[col * 68 + a] = Wih[row * 320 + 256 + a];
    }
    #pragma unroll 4
    for (int q = 0; q < 64; q++) {
        int idx = q * 256 + tid;
        int col = idx >> 8, k = idx & 255;
        int row = (col >> 4) * 1024 + jb * 16 + (col & 15);
        int sw  = ((k >> 3) & 7) ^ (col & 7);
        wp[(k >> 6) * 4096 + col * 64 + sw * 8 + (k & 7)] = __float2half(Wih[row * 320 + k]);
    }
    __syncthreads();

    const int col = tid & 63;
    const int hq  = tid >> 6;
    const int row = (col >> 4) * 1024 + jb * 16 + (col & 15);
    for (int hc = 0; hc < 16; hc++) {
        #pragma unroll 4
        for (int q = 0; q < 16; q++) {
            int idx = q * 256 + tid;
            int a = idx >> 6, h = idx & 63;
            Wc[a * 68 + h] = Wout[a * 1024 + hc * 64 + h];
        }
        __syncthreads();
        #pragma unroll 2
        for (int i = 0; i < 16; i++) {
            int h  = hq * 16 + i;
            int hh = hc * 64 + h;
            float fold = 0.f;
            #pragma unroll 8
            for (int a = 0; a < 64; a++)
                fold = fmaf(As[col * 68 + a], Wc[a * 68 + h], fold);
            float val = Whh[row * 1024 + hh] + fold;
            int k = 256 + hh;
            int sw = ((k >> 3) & 7) ^ (col & 7);
            wp[(k >> 6) * 4096 + col * 64 + sw * 8 + (k & 7)] = __float2half(val);
        }
        __syncthreads();
    }
}

// ---------------- kernel 2b: pack Wout fp16 swizzled image for finalout ----------------
__global__ void wfin_kernel(const float* __restrict__ Wout)
{
    const int cc  = blockIdx.x;
    const int tid = threadIdx.x;
    __half* wp = g_Wfin + cc * 4096;
    #pragma unroll
    for (int q = 0; q < 16; q++) {
        int idx = q * 256 + tid;
        int n = idx >> 6, kk = idx & 63;
        int sw = ((kk >> 3) & 7) ^ (n & 7);
        wp[n * 64 + sw * 8 + (kk & 7)] = __float2half(Wout[n * 1024 + cc * 64 + kk]);
    }
}

// ---------------- kernel 3: mlp via fp16 mma -> g_Ah[s][b][k], 2 timesteps/block ----------------
__global__ void __launch_bounds__(512, 1)
mlp_kernel(const float* __restrict__ observe,
           const float* __restrict__ obstacle,
           const float* __restrict__ mask)
{
    extern __shared__ __half msm[];
    __shared__ float sbc[MLP_O];
    const int tid  = threadIdx.x;
    const int lane = tid & 31;
    const int w    = tid >> 5;               // 0..15
    const int s0   = (blockIdx.x >> 1) * 2;  // 2 timesteps per block
    const int b0   = (blockIdx.x & 1) * 128;

    const uint32_t sbase = smem_u32(msm);
    const uint32_t wbase = sbase;            // Wc image: 3 chunks x 32768 B
    const uint32_t xbase = sbase + MW_BYTES; // X tile:  3 chunks x 16384 B

    // load Wc image (96 KB) once
    for (int u = tid; u < MW_BYTES / 16; u += 512)
        cpasync16(wbase + u * 16, g_Wmlp + (size_t)u * 8);
    CP_COMMIT();
    for (int i = tid; i < MLP_O; i += 512) sbc[i] = g_bc[i];
    CP_WAIT(0);

    const int m0 = (w & 7) * 16;
    const int nb = (w >> 3) * 128;

    for (int s2 = 0; s2 < 2; s2++) {
        const int s = s0 + s2;
        __syncthreads();   // previous iteration's X reads done before overwrite

        // build X tile: 128 tokens x 192 features, swizzled fp16
        for (int idx = tid; idx < 128 * IN_D; idx += 512) {
            int r = idx / IN_D, k = idx - r * IN_D;
            int p = (b0 + r) * 128 + s;
            float v;
            if (k < 64) v = observe[p * 64 + k];
            else {
                int kk2 = k - 64;
                v = obstacle[p * 128 + kk2] * mask[p * 8 + (kk2 >> 4)];
            }
            int ch = k >> 6, kk = k & 63;
            uint32_t addr = xbase + ch * 16384 + r * 128
                          + ((((kk >> 3) & 7) ^ (r & 7)) << 4) + (kk & 7) * 2;
            *(__half*)(msm + (addr - sbase) / 2) = __float2half(v);
        }
        __syncthreads();

        float acc[16][4];
        #pragma unroll
        for (int nt = 0; nt < 16; nt++)
            #pragma unroll
            for (int r = 0; r < 4; r++) acc[nt][r] = 0.f;

        for (int ch = 0; ch < 3; ch++) {
            uint32_t sA = xbase + ch * 16384;
            uint32_t sB = wbase + ch * 32768;
            #pragma unroll
            for (int ks = 0; ks < 4; ks++) {
                const int ku0 = ks * 2;
                uint32_t af[4], bf[8][4];
                {
                    int lr = m0 + (lane & 15);
                    int ku = (lane >> 4) + ku0;
                    ldsm4(af, sA + lr * 128 + ((ku ^ (lr & 7)) << 4));
                }
                #pragma unroll
                for (int nh = 0; nh < 8; nh++) {
                    int n  = nb + nh * 16 + (lane & 7) + ((lane >> 4) << 3);
                    int ku = ((lane & 8) >> 3) + ku0;
                    ldsm4(bf[nh], sB + n * 128 + ((ku ^ (n & 7)) << 4));
                }
                #pragma unroll
                for (int nt = 0; nt < 16; nt++)
                    mma_f16(acc[nt], af[0], af[1], af[2], af[3],
                            bf[nt >> 1][(nt & 1) * 2], bf[nt >> 1][(nt & 1) * 2 + 1]);
            }
        }

        // epilogue: bias + relu -> fp16 pairs -> g_Ah[s][b][col]
        const int r0 = m0 + (lane >> 2);
        __half* dst = g_Ah + (size_t)s * BB * K2 + (size_t)b0 * K2;
        #pragma unroll
        for (int nt = 0; nt < 16; nt++) {
            int a0 = nb + nt * 8 + 2 * (lane & 3);
            float bv0 = sbc[a0], bv1 = sbc[a0 + 1];
            __half2 v0 = __floats2half2_rn(fmaxf(acc[nt][0] + bv0, 0.f),
                                           fmaxf(acc[nt][1] + bv1, 0.f));
            __half2 v1 = __floats2half2_rn(fmaxf(acc[nt][2] + bv0, 0.f),
                                           fmaxf(acc[nt][3] + bv1, 0.f));
            *(__half2*)(dst + (size_t)r0 * K2 + a0)       = v0;
            *(__half2*)(dst + (size_t)(r0 + 8) * K2 + a0) = v1;
        }
    }
}

// ---------------- kernel 4: persistent LSTM (16 warps, tree barrier) ----------------
__global__ void __launch_bounds__(NTHR, 1)
lstm_kernel(int dummy)
{
    extern __shared__ __half smh[];
    float* sg = (float*)(smh + W_HALFS);
    __shared__ float sbias[2][64];

    const int tid  = threadIdx.x;
    const int cta  = blockIdx.x;
    const int mh   = cta & 1;
    const int jb   = cta >> 1;
    const int j0   = jb * 16;
    const int lane = tid & 31;
    const int w    = tid >> 5;
    const int wm   = w & 3;
    const int wn   = w >> 2;
    const int grp  = cta >> 3;
    unsigned gen = *((volatile unsigned*)&g_gen);

    const uint32_t sbase = smem_u32(smh);
    const uint32_t wbase = sbase;
    const uint32_t abase = sbase + W_HALFS * 2;

    {
        const __half* src = g_Wph + (size_t)jb * W_HALFS;
        for (int u = tid; u < W_HALFS / 8; u += NTHR)
            cpasync16(wbase + u * 16, src + (size_t)u * 8);
        CP_COMMIT();
    }

    const int gt = cta * NTHR + tid;
    for (int i = gt; i < (HH * BB) / 2; i += NCTA * NTHR) {
        int b = i >> 9, off = (i & 511) * 2;
        *(uint32_t*)&g_Ah[(size_t)b * K2 + 256 + off] = 0u;
    }
    if (gt < 16 * 32) { g_leafp[gt] = 0u; g_relp[gt] = 0u; }
    if (gt == 16 * 32) g_root = 0u;
    if (tid < 64) {
        int gate = tid >> 4, jl = tid & 15;
        sbias[0][tid] = g_bias0[gate * 1024 + j0 + jl];
        sbias[1][tid] = g_bias1[gate * 1024 + j0 + jl];
    }
    float c_reg[4];
    #pragma unroll
    for (int q = 0; q < 4; q++) c_reg[q] = 0.f;
    CP_WAIT(0);
    grid_barrier(gen);

    #define BAR_QUAD() asm volatile("bar.sync %0, %1;" :: "r"(wm + 1), "r"(128) : "memory")

    auto prefA = [&](const __half* Asl, int cc) {
        uint32_t sd = abase + (wm * NSTG + (cc & 3)) * ASTG2_B;
        const __half* src = Asl + (size_t)(wm * 32) * K2 + cc * CK;
        #pragma unroll
        for (int i = 0; i < 2; i++) {
            int idx = i * 128 + wn * 32 + lane;
            int r = idx >> 3, u = idx & 7;
            cpasync16(sd + r * 128 + ((u ^ (r & 7)) << 4), src + (size_t)r * K2 + u * 8);
        }
        CP_COMMIT();
    };

    auto do_chunk = [&](int cc, float (&acc)[2][2][4]) {
        uint32_t sA = abase + (wm * NSTG + (cc & 3)) * ASTG2_B;
        uint32_t sB = wbase + cc * 8192;
        #pragma unroll
        for (int ks = 0; ks < 4; ks++) {
            const int ku0 = ks * 2;
            uint32_t af[2][4], bf[4];
            #pragma unroll
            for (int mt = 0; mt < 2; mt++) {
                int lr = mt * 16 + (lane & 15);
                int ku = (lane >> 4) + ku0;
                ldsm4(af[mt], sA + lr * 128 + ((ku ^ (lr & 7)) << 4));
            }
            {
                int n  = wn * 16 + (lane & 7) + ((lane >> 4) << 3);
                int ku = ((lane & 8) >> 3) + ku0;
                ldsm4(bf, sB + n * 128 + ((ku ^ (n & 7)) << 4));
            }
            #pragma unroll
            for (int mt = 0; mt < 2; mt++)
                #pragma unroll
                for (int nt = 0; nt < 2; nt++)
                    mma_f16(acc[mt][nt],
                            af[mt][0], af[mt][1], af[mt][2], af[mt][3],
                            bf[nt * 2], bf[nt * 2 + 1]);
        }
    };

    prefA(g_Ah + (size_t)mh * 128 * K2, 0);
    prefA(g_Ah + (size_t)mh * 128 * K2, 1);
    prefA(g_Ah + (size_t)mh * 128 * K2, 2);

    for (int t = 0; t < SS; ++t) {
        const __half* Asl = g_Ah + (size_t)t * BB * K2 + (size_t)mh * 128 * K2;

        float acc[2][2][4];
        #pragma unroll
        for (int mt = 0; mt < 2; mt++)
            #pragma unroll
            for (int nt = 0; nt < 2; nt++)
                #pragma unroll
                for (int r = 0; r < 4; r++) acc[mt][nt][r] = 0.f;

        for (int cc = 0; cc < 4; cc++) {
            if (cc == 0) prefA(Asl, 3);
            if      (cc == 0) CP_WAIT(3);
            else if (cc == 1) CP_WAIT(2);
            else if (cc == 2) CP_WAIT(1);
            else              CP_WAIT(0);
            BAR_QUAD();
            do_chunk(cc, acc);
        }

        if (t > 0) {
            if (tid == 0) {
                const volatile unsigned* rl = &g_relp[grp * 32];
                while (*rl < (unsigned)t) { }
                __threadfence();
            }
        }
        __syncthreads();

        prefA(Asl, 4);
        prefA(Asl, 5);
        prefA(Asl, 6);
        for (int cc = 4; cc < NCH; cc++) {
            if (cc + 3 < NCH) prefA(Asl, cc + 3);
            if      (cc <  NCH - 3) CP_WAIT(3);
            else if (cc == NCH - 3) CP_WAIT(2);
            else if (cc == NCH - 2) CP_WAIT(1);
            else                    CP_WAIT(0);
            BAR_QUAD();
            do_chunk(cc, acc);
        }
        __syncthreads();

        #pragma unroll
        for (int mt = 0; mt < 2; mt++) {
            int m0 = wm * 32 + mt * 16 + (lane >> 2);
            #pragma unroll
            for (int nt = 0; nt < 2; nt++) {
                int c0 = wn * 16 + nt * 8 + 2 * (lane & 3);
                sg[c0 * 132 + m0]           = acc[mt][nt][0];
                sg[(c0 + 1) * 132 + m0]     = acc[mt][nt][1];
                sg[c0 * 132 + m0 + 8]       = acc[mt][nt][2];
                sg[(c0 + 1) * 132 + m0 + 8] = acc[mt][nt][3];
            }
        }
        __syncthreads();

        {
            const int b  = tid & 127;
            const int js = (tid >> 7) * 4;
            const float* bs = sbias[t > 0 ? 1 : 0];
            __align__(8) __half hbuf[4];
            #pragma unroll
            for (int q = 0; q < 4; q++) {
                int jl = js + q;
                float iv = fast_sig (sg[jl * 132 + b]        + bs[jl]);
                float fv = fast_sig (sg[(16 + jl) * 132 + b] + bs[16 + jl]);
                float gv = fast_tanh(sg[(32 + jl) * 132 + b] + bs[32 + jl]);
                float ov = fast_sig (sg[(48 + jl) * 132 + b] + bs[48 + jl]);
                float cnew = fmaf(fv, c_reg[q], iv * gv);
                c_reg[q] = cnew;
                hbuf[q] = __float2half(ov * fast_tanh(cnew));
            }
            __half* hd = g_Ah + (size_t)(t + 1) * BB * K2
                       + (size_t)(mh * 128 + b) * K2 + 256 + j0 + js;
            *(uint2*)hd = *(uint2*)hbuf;
        }
        __syncthreads();

        if (t + 1 < SS) {
            if (tid == 0) {
                __threadfence();
                unsigned lo = atomicAdd(&g_leafp[grp * 32], 1u);
                if (((lo + 1) & 7u) == 0u) {
                    unsigned ro = atomicAdd(&g_root, 1u);
                    if (((ro + 1) & 15u) == 0u) {
                        unsigned rv = (ro + 1) >> 4;
                        __threadfence();
                        #pragma unroll
                        for (int i = 0; i < 16; i++)
                            *((volatile unsigned*)&g_relp[i * 32]) = rv;
                    }
                }
            }
            const __half* AslN = Asl + (size_t)BB * K2;
            prefA(AslN, 0);
            prefA(AslN, 1);
            prefA(AslN, 2);
        }
    }
    #undef BAR_QUAD
}

// ---------------- kernel 5: out = h_t @ Wout^T + bout (fp16 mma, 2 timesteps/block) ----------------
__global__ void __launch_bounds__(256, 1)
finalout_kernel(const float* __restrict__ bout, float* __restrict__ dout)
{
    extern __shared__ __half fsm[];
    const int tid  = threadIdx.x;
    const int lane = tid & 31;
    const int w    = tid >> 5;
    const int t0   = (blockIdx.x >> 1) * 2;  // 2 timesteps per block
    const int b0   = (blockIdx.x & 1) * 128;

    const uint32_t sbase = smem_u32(fsm);
    const uint32_t wbase = sbase;
    const uint32_t hbase = sbase + FW_HALFS * 2;

    // load Wout image (128 KB) once
    for (int u = tid; u < FW_HALFS / 8; u += 256)
        cpasync16(wbase + u * 16, g_Wfin + (size_t)u * 8);

    auto prefH = [&](const __half* hsl, int cc, int stg) {
        uint32_t sd = hbase + (stg & 1) * FSTG_B;
        #pragma unroll
        for (int i = 0; i < 4; i++) {
            int idx = i * 256 + tid;
            int r = idx >> 3, u = idx & 7;
            cpasync16(sd + r * 128 + ((u ^ (r & 7)) << 4),
                      hsl + (size_t)r * K2 + cc * 64 + u * 8);
        }
        CP_COMMIT();
    };

    const int m0 = w * 16 + (lane >> 2);

    // continuous 32-chunk pipeline across both timesteps
    const __half* hsl0 = g_Ah + (size_t)(t0 + 1) * BB * K2 + (size_t)b0 * K2 + 256;
    const __half* hsl1 = hsl0 + (size_t)BB * K2;
    prefH(hsl0, 0, 0);

    for (int t2 = 0; t2 < 2; t2++) {
        const __half* hsl = t2 ? hsl1 : hsl0;
        float acc[8][4];
        #pragma unroll
        for (int nt = 0; nt < 8; nt++)
            #pragma unroll
            for (int r = 0; r < 4; r++) acc[nt][r] = 0.f;

        for (int cc = 0; cc < 16; cc++) {
            int gstg = t2 * 16 + cc;
            // prefetch next chunk (possibly of next timestep)
            if (gstg + 1 < 32) {
                const __half* nsl = (gstg + 1 < 16) ? hsl0 : hsl1;
                prefH(nsl, (gstg + 1) & 15, gstg + 1);
                CP_WAIT(1);
            } else {
                CP_WAIT(0);
            }
            __syncthreads();
            uint32_t sA = hbase + (gstg & 1) * FSTG_B;
            uint32_t sB = wbase + cc * 8192;
            #pragma unroll
            for (int ks = 0; ks < 4; ks++) {
                const int ku0 = ks * 2;
                uint32_t af[4], bf[4][4];
                {
                    int lr = w * 16 + (lane & 15);
                    int ku = (lane >> 4) + ku0;
                    ldsm4(af, sA + lr * 128 + ((ku ^ (lr & 7)) << 4));
                }
                #pragma unroll
                for (int nh = 0; nh < 4; nh++) {
                    int n  = nh * 16 + (lane & 7) + ((lane >> 4) << 3);
                    int ku = ((lane & 8) >> 3) + ku0;
                    ldsm4(bf[nh], sB + n * 128 + ((ku ^ (n & 7)) << 4));
                }
                #pragma unroll
                for (int nt = 0; nt < 8; nt++)
                    mma_f16(acc[nt], af[0], af[1], af[2], af[3],
                            bf[nt >> 1][(nt & 1) * 2], bf[nt >> 1][(nt & 1) * 2 + 1]);
            }
            __syncthreads();
        }

        const int tt = t0 + t2;
        #pragma unroll
        for (int nt = 0; nt < 8; nt++) {
            int a0 = nt * 8 + 2 * (lane & 3);
            float bv0 = __ldg(bout + a0), bv1 = __ldg(bout + a0 + 1);
            float* d0 = dout + (size_t)(b0 + m0) * SS * AA + tt * AA + a0;
            float* d1 = dout + (size_t)(b0 + m0 + 8) * SS * AA + tt * AA + a0;
            d0[0] = acc[nt][0] + bv0;
            d0[1] = acc[nt][1] + bv1;
            d1[0] = acc[nt][2] + bv0;
            d1[1] = acc[nt][3] + bv1;
        }
    }
}

// ---------------- launch ----------------
extern "C" void kernel_launch(void* const* d_in, const int* in_sizes, int n_in,
                              void* d_out, int out_size)
{
    const float* observe  = (const float*)d_in[0];
    const float* obstacle = (const float*)d_in[1];
    const float* mask     = (const float*)d_in[2];
    const float* W1       = (const float*)d_in[3];
    const float* b1       = (const float*)d_in[4];
    const float* W2       = (const float*)d_in[5];
    const float* b2       = (const float*)d_in[6];
    const float* W_ih     = (const float*)d_in[7];
    const float* b_ih     = (const float*)d_in[8];
    const float* W_hh     = (const float*)d_in[9];
    const float* b_hh     = (const float*)d_in[10];
    const float* W_out    = (const float*)d_in[11];
    const float* b_out    = (const float*)d_in[12];
    float* out = (float*)d_out;

    cudaFuncSetAttribute(lstm_kernel, cudaFuncAttributeMaxDynamicSharedMemorySize, SMEM_BYTES);
    cudaFuncSetAttribute(finalout_kernel, cudaFuncAttributeMaxDynamicSharedMemorySize, FOUT_SMEM);
    cudaFuncSetAttribute(mlp_kernel, cudaFuncAttributeMaxDynamicSharedMemorySize, MLP_SMEM);

    bias_kernel<<<16, 256>>>(W2, b1, b2, b_ih, b_hh, W_ih, b_out);
    collapse_kernel<<<IN_D, 256>>>(W1, W2);
    wprep_kernel<<<64, 256>>>(W_ih, W_hh, W_out);
    wfin_kernel<<<16, 256>>>(W_out);
    mlp_kernel<<<SS, 512, MLP_SMEM>>>(observe, obstacle, mask);
    lstm_kernel<<<NCTA, NTHR, SMEM_BYTES>>>(0);
    finalout_kernel<<<SS, 256, FOUT_SMEM>>>(b_out, out);
}